// round 2
// baseline (speedup 1.0000x reference)
#include <cuda_runtime.h>
#include <math.h>

#define T_STEPS 1024
#define BATCH   64
#define IDIM    512
#define HDIM    512
#define G4      2048   // 4*H

// Scratch: x_proj [T, B, 4H] fp32 (512 MB) — __device__ global per harness rules.
__device__ float g_xproj[(size_t)T_STEPS * BATCH * G4];
__device__ unsigned int g_bar;

// ---------------- f32x2 packed-FMA helpers (Blackwell FFMA2) ----------------
__device__ __forceinline__ unsigned long long pk2(float lo, float hi) {
    unsigned long long r;
    asm("mov.b64 %0, {%1, %2};" : "=l"(r) : "f"(lo), "f"(hi));
    return r;
}
__device__ __forceinline__ void upk2(unsigned long long v, float& lo, float& hi) {
    asm("mov.b64 {%0, %1}, %2;" : "=f"(lo), "=f"(hi) : "l"(v));
}
__device__ __forceinline__ unsigned long long fma2(unsigned long long a,
                                                   unsigned long long b,
                                                   unsigned long long c) {
    unsigned long long d;
    asm("fma.rn.f32x2 %0, %1, %2, %3;" : "=l"(d) : "l"(a), "l"(b), "l"(c));
    return d;
}

__global__ void reset_bar_kernel() { g_bar = 0u; }

// ---------------------------------------------------------------------------
// Kernel 1: x_proj[m, g] = sum_k input[m,k] * W_ih[g,k] + b_ih[g] + b_hh[g]
// M = 65536, N = 2048, K = 512. Both operands K-major (NT GEMM).
// 128x128 tile, K-tile 8, 256 threads, 8x8 per-thread microtile, FFMA2.
// ---------------------------------------------------------------------------
__global__ void __launch_bounds__(256) xproj_kernel(
    const float* __restrict__ A, const float* __restrict__ W,
    const float* __restrict__ bih, const float* __restrict__ bhh)
{
    __shared__ float As[8][132];
    __shared__ float Bs[8][132];
    const int tid  = threadIdx.x;
    const int m0   = blockIdx.y * 128;
    const int n0   = blockIdx.x * 128;
    const int lrow = tid >> 1;
    const int lk   = (tid & 1) * 4;
    const float* ag = A + (size_t)(m0 + lrow) * IDIM + lk;
    const float* bg = W + (size_t)(n0 + lrow) * IDIM + lk;
    const int tx = tid & 15;
    const int ty = tid >> 4;

    unsigned long long acc[8][4];
#pragma unroll
    for (int i = 0; i < 8; i++)
#pragma unroll
        for (int j = 0; j < 4; j++) acc[i][j] = 0ull;

    float4 av = *(const float4*)ag;
    float4 bv = *(const float4*)bg;

    for (int kt = 0; kt < 64; kt++) {
        As[lk + 0][lrow] = av.x; As[lk + 1][lrow] = av.y;
        As[lk + 2][lrow] = av.z; As[lk + 3][lrow] = av.w;
        Bs[lk + 0][lrow] = bv.x; Bs[lk + 1][lrow] = bv.y;
        Bs[lk + 2][lrow] = bv.z; Bs[lk + 3][lrow] = bv.w;
        __syncthreads();

        float4 avn = make_float4(0.f, 0.f, 0.f, 0.f);
        float4 bvn = avn;
        if (kt < 63) {
            avn = *(const float4*)(ag + (kt + 1) * 8);
            bvn = *(const float4*)(bg + (kt + 1) * 8);
        }

#pragma unroll
        for (int k = 0; k < 8; k++) {
            float4 a0 = *(const float4*)&As[k][ty * 8];
            float4 a1 = *(const float4*)&As[k][ty * 8 + 4];
            float4 b0 = *(const float4*)&Bs[k][tx * 8];
            float4 b1 = *(const float4*)&Bs[k][tx * 8 + 4];
            unsigned long long bb0 = pk2(b0.x, b0.y), bb1 = pk2(b0.z, b0.w);
            unsigned long long bb2 = pk2(b1.x, b1.y), bb3 = pk2(b1.z, b1.w);
            float aa[8] = {a0.x, a0.y, a0.z, a0.w, a1.x, a1.y, a1.z, a1.w};
#pragma unroll
            for (int i = 0; i < 8; i++) {
                unsigned long long ad = pk2(aa[i], aa[i]);
                acc[i][0] = fma2(ad, bb0, acc[i][0]);
                acc[i][1] = fma2(ad, bb1, acc[i][1]);
                acc[i][2] = fma2(ad, bb2, acc[i][2]);
                acc[i][3] = fma2(ad, bb3, acc[i][3]);
            }
        }
        __syncthreads();
        av = avn; bv = bvn;
    }

    float bias[8];
#pragma unroll
    for (int j = 0; j < 8; j++) {
        int n = n0 + tx * 8 + j;
        bias[j] = bih[n] + bhh[n];
    }
#pragma unroll
    for (int i = 0; i < 8; i++) {
        int m = m0 + ty * 8 + i;
        float o[8];
        upk2(acc[i][0], o[0], o[1]);
        upk2(acc[i][1], o[2], o[3]);
        upk2(acc[i][2], o[4], o[5]);
        upk2(acc[i][3], o[6], o[7]);
#pragma unroll
        for (int j = 0; j < 8; j++) o[j] += bias[j];
        float4* dst = (float4*)(g_xproj + (size_t)m * G4 + n0 + tx * 8);
        dst[0] = make_float4(o[0], o[1], o[2], o[3]);
        dst[1] = make_float4(o[4], o[5], o[6], o[7]);
    }
}

// ---------------------------------------------------------------------------
// Kernel 2: persistent reverse-scan recurrence.
// 128 CTAs; CTA k owns h-columns j0 = 4k..4k+3 (gate cols {j0+jj + gate*512}).
// W_hh slice (16 cols x 512) lives in REGISTERS (64 floats/thread).
// Previous h is read from `out` (outputs[t+1] == carry h); one grid barrier
// per step via atomic counter.
// Thread map (512 thr): c = tid&15 (gate col: gate*4+jj), s = (tid>>4)&7
// (K-slice of 64), bg = tid>>7 (batch group of 16).
// ---------------------------------------------------------------------------
__global__ void __launch_bounds__(512, 1) recur_kernel(
    const float* __restrict__ h0, const float* __restrict__ c0,
    const float* __restrict__ Whh, float* __restrict__ out)
{
    extern __shared__ float sm[];
    float* h_s    = sm;            // 64*512      = 32768 floats
    float* xp_s   = sm + 32768;    // 64*16       =  1024
    float* part_s = sm + 33792;    // 64*16*9     =  9216 (pad 9 to dodge banks)
    float* pre_s  = sm + 43008;    // 64*16       =  1024
    float* c_s    = sm + 44032;    // 64*4        =   256   total 44288 floats

    const int tid  = threadIdx.x;
    const int c    = tid & 15;
    const int s    = (tid >> 4) & 7;
    const int bg   = tid >> 7;
    const int j0   = blockIdx.x * 4;
    const int gate = c >> 2;
    const int jj   = c & 3;
    const int gcol = gate * HDIM + j0 + jj;

    // W_hh[gcol][s*64 .. s*64+63] -> 32 packed f32x2 registers (loaded once)
    unsigned long long w[32];
    {
        const float4* wp = (const float4*)(Whh + (size_t)gcol * HDIM + s * 64);
#pragma unroll
        for (int q = 0; q < 16; q++) {
            float4 v = wp[q];
            w[2 * q]     = pk2(v.x, v.y);
            w[2 * q + 1] = pk2(v.z, v.w);
        }
    }
    if (tid < 256)
        c_s[tid] = c0[(size_t)(tid >> 2) * HDIM + j0 + (tid & 3)];

    const unsigned nCTA = gridDim.x;

    for (int t = T_STEPS - 1; t >= 0; t--) {
        // ---- stage previous h and this step's x_proj slice into SMEM ----
        const float* hsrc = (t == T_STEPS - 1)
                              ? h0
                              : (out + (size_t)(t + 1) * (BATCH * HDIM));
        const float4* hs4 = (const float4*)hsrc;
        float4* hd4 = (float4*)h_s;
#pragma unroll
        for (int q = 0; q < 16; q++)
            hd4[tid + q * 512] = hs4[tid + q * 512];
        if (tid < 256) {
            int b = tid >> 2, g = tid & 3;
            float4 v = *(const float4*)(g_xproj + (size_t)(t * BATCH + b) * G4
                                        + g * HDIM + j0);
            ((float4*)xp_s)[tid] = v;   // xp_s[b*16 + g*4 + jj]
        }
        __syncthreads();

        // ---- phase A: K-sliced partial dot products, W from registers ----
#pragma unroll 1
        for (int bi = 0; bi < 16; bi++) {
            int b = bg * 16 + bi;
            const float4* hp = (const float4*)(h_s + b * 512 + s * 64);
            unsigned long long acc = 0ull;
#pragma unroll
            for (int q = 0; q < 16; q++) {
                float4 hv = hp[q];
                acc = fma2(pk2(hv.x, hv.y), w[2 * q],     acc);
                acc = fma2(pk2(hv.z, hv.w), w[2 * q + 1], acc);
            }
            float lo, hi; upk2(acc, lo, hi);
            part_s[(b * 16 + c) * 9 + s] = lo + hi;
        }
        __syncthreads();

        // ---- reduce the 8 K-slices, add x_proj ----
#pragma unroll
        for (int u = tid; u < 1024; u += 512) {
            const float* pp = part_s + u * 9;
            float r = ((pp[0] + pp[1]) + (pp[2] + pp[3])) +
                      ((pp[4] + pp[5]) + (pp[6] + pp[7]));
            pre_s[u] = xp_s[u] + r;
        }
        __syncthreads();

        // ---- elementwise: all-sigmoid subLSTM cell update ----
        if (tid < 256) {
            int b = tid >> 2, j = tid & 3;
            float gi = 1.0f / (1.0f + expf(-pre_s[b * 16 + 0  + j]));
            float gf = 1.0f / (1.0f + expf(-pre_s[b * 16 + 4  + j]));
            float gz = 1.0f / (1.0f + expf(-pre_s[b * 16 + 8  + j]));
            float go = 1.0f / (1.0f + expf(-pre_s[b * 16 + 12 + j]));
            float cn = gf * c_s[tid] + gz - gi;
            c_s[tid] = cn;
            float hn = 1.0f / (1.0f + expf(-cn)) - go;
            out[(size_t)t * (BATCH * HDIM) + b * HDIM + j0 + j] = hn;
            if (t == 0) {
                const size_t base = (size_t)T_STEPS * BATCH * HDIM;
                out[base + b * HDIM + j0 + j] = hn;                 // h_f
                out[base + BATCH * HDIM + b * HDIM + j0 + j] = cn;  // c_f
            }
        }
        __syncthreads();

        // ---- grid barrier (release h writes / acquire for next read) ----
        if (tid == 0) {
            __threadfence();
            atomicAdd(&g_bar, 1u);
            unsigned target = (unsigned)(T_STEPS - t) * nCTA;
            volatile unsigned* p = &g_bar;
            while (*p < target) { }
            __threadfence();
        }
        __syncthreads();
    }
}

// ---------------------------------------------------------------------------
extern "C" void kernel_launch(void* const* d_in, const int* in_sizes, int n_in,
                              void* d_out, int out_size)
{
    const float* input = (const float*)d_in[0];
    const float* h0    = (const float*)d_in[1];
    const float* c0    = (const float*)d_in[2];
    const float* Wih   = (const float*)d_in[3];
    const float* Whh   = (const float*)d_in[4];
    const float* bih   = (const float*)d_in[5];
    const float* bhh   = (const float*)d_in[6];
    float* out = (float*)d_out;

    const size_t smem_bytes = 44288 * sizeof(float);   // 177,152 B
    static int configured = 0;
    if (!configured) {
        cudaFuncSetAttribute(recur_kernel,
                             cudaFuncAttributeMaxDynamicSharedMemorySize,
                             (int)smem_bytes);
        configured = 1;
    }

    reset_bar_kernel<<<1, 1>>>();
    xproj_kernel<<<dim3(G4 / 128, (T_STEPS * BATCH) / 128), 256>>>(
        input, Wih, bih, bhh);
    recur_kernel<<<HDIM / 4, 512, smem_bytes>>>(h0, c0, Whh, out);
}

// round 3
// speedup vs baseline: 1.1110x; 1.1110x over previous
#include <cuda_runtime.h>
#include <math.h>

#define T_STEPS 1024
#define BATCH   64
#define IDIM    512
#define HDIM    512
#define G4      2048   // 4*H

// Scratch: x_proj [T, B, 4H] fp32 (512 MB) — __device__ global per harness rules.
__device__ float g_xproj[(size_t)T_STEPS * BATCH * G4];
__device__ unsigned int g_bar;
__device__ unsigned int g_done;

// ---------------- f32x2 packed-FMA helpers (Blackwell FFMA2) ----------------
__device__ __forceinline__ unsigned long long pk2(float lo, float hi) {
    unsigned long long r;
    asm("mov.b64 %0, {%1, %2};" : "=l"(r) : "f"(lo), "f"(hi));
    return r;
}
__device__ __forceinline__ void upk2(unsigned long long v, float& lo, float& hi) {
    asm("mov.b64 {%0, %1}, %2;" : "=f"(lo), "=f"(hi) : "l"(v));
}
__device__ __forceinline__ unsigned long long fma2(unsigned long long a,
                                                   unsigned long long b,
                                                   unsigned long long c) {
    unsigned long long d;
    asm("fma.rn.f32x2 %0, %1, %2, %3;" : "=l"(d) : "l"(a), "l"(b), "l"(c));
    return d;
}
__device__ __forceinline__ float sigf(float x) {
    return 1.0f / (1.0f + expf(-x));
}

// ---------------------------------------------------------------------------
// Kernel 1: x_proj[m, g] = sum_k input[m,k] * W_ih[g,k] + b_ih[g] + b_hh[g]
// M = 65536, N = 2048, K = 512. NT GEMM, 128x128 tile, FFMA2 microkernel.
// ---------------------------------------------------------------------------
__global__ void __launch_bounds__(256) xproj_kernel(
    const float* __restrict__ A, const float* __restrict__ W,
    const float* __restrict__ bih, const float* __restrict__ bhh)
{
    __shared__ float As[8][132];
    __shared__ float Bs[8][132];
    const int tid  = threadIdx.x;
    const int m0   = blockIdx.y * 128;
    const int n0   = blockIdx.x * 128;
    const int lrow = tid >> 1;
    const int lk   = (tid & 1) * 4;
    const float* ag = A + (size_t)(m0 + lrow) * IDIM + lk;
    const float* bg = W + (size_t)(n0 + lrow) * IDIM + lk;
    const int tx = tid & 15;
    const int ty = tid >> 4;

    unsigned long long acc[8][4];
#pragma unroll
    for (int i = 0; i < 8; i++)
#pragma unroll
        for (int j = 0; j < 4; j++) acc[i][j] = 0ull;

    float4 av = *(const float4*)ag;
    float4 bv = *(const float4*)bg;

    for (int kt = 0; kt < 64; kt++) {
        As[lk + 0][lrow] = av.x; As[lk + 1][lrow] = av.y;
        As[lk + 2][lrow] = av.z; As[lk + 3][lrow] = av.w;
        Bs[lk + 0][lrow] = bv.x; Bs[lk + 1][lrow] = bv.y;
        Bs[lk + 2][lrow] = bv.z; Bs[lk + 3][lrow] = bv.w;
        __syncthreads();

        float4 avn = make_float4(0.f, 0.f, 0.f, 0.f);
        float4 bvn = avn;
        if (kt < 63) {
            avn = *(const float4*)(ag + (kt + 1) * 8);
            bvn = *(const float4*)(bg + (kt + 1) * 8);
        }

#pragma unroll
        for (int k = 0; k < 8; k++) {
            float4 a0 = *(const float4*)&As[k][ty * 8];
            float4 a1 = *(const float4*)&As[k][ty * 8 + 4];
            float4 b0 = *(const float4*)&Bs[k][tx * 8];
            float4 b1 = *(const float4*)&Bs[k][tx * 8 + 4];
            unsigned long long bb0 = pk2(b0.x, b0.y), bb1 = pk2(b0.z, b0.w);
            unsigned long long bb2 = pk2(b1.x, b1.y), bb3 = pk2(b1.z, b1.w);
            float aa[8] = {a0.x, a0.y, a0.z, a0.w, a1.x, a1.y, a1.z, a1.w};
#pragma unroll
            for (int i = 0; i < 8; i++) {
                unsigned long long ad = pk2(aa[i], aa[i]);
                acc[i][0] = fma2(ad, bb0, acc[i][0]);
                acc[i][1] = fma2(ad, bb1, acc[i][1]);
                acc[i][2] = fma2(ad, bb2, acc[i][2]);
                acc[i][3] = fma2(ad, bb3, acc[i][3]);
            }
        }
        __syncthreads();
        av = avn; bv = bvn;
    }

    float bias[8];
#pragma unroll
    for (int j = 0; j < 8; j++) {
        int n = n0 + tx * 8 + j;
        bias[j] = bih[n] + bhh[n];
    }
#pragma unroll
    for (int i = 0; i < 8; i++) {
        int m = m0 + ty * 8 + i;
        float o[8];
        upk2(acc[i][0], o[0], o[1]);
        upk2(acc[i][1], o[2], o[3]);
        upk2(acc[i][2], o[4], o[5]);
        upk2(acc[i][3], o[6], o[7]);
#pragma unroll
        for (int j = 0; j < 8; j++) o[j] += bias[j];
        float4* dst = (float4*)(g_xproj + (size_t)m * G4 + n0 + tx * 8);
        dst[0] = make_float4(o[0], o[1], o[2], o[3]);
        dst[1] = make_float4(o[4], o[5], o[6], o[7]);
    }
}

// ---------------------------------------------------------------------------
// Kernel 2: persistent reverse-scan recurrence, batch x column 2D partition.
// Grid: (32 col-groups, 4 batch-groups) = 128 CTAs.
// CTA: batches B0..B0+15, h-cols j0..j0+15 (=> 64 gate cols).
// Thread map (512): cq = tid&63 (local gate col), s = tid>>6 (K-slice of 64).
// W_hh[gc][s*64..+63] in registers (32 u64). h loads are warp-wide SMEM
// broadcasts of pre-paired u64x2 — zero packing movs.
// ---------------------------------------------------------------------------
__global__ void __launch_bounds__(512, 1) recur_kernel(
    const float* __restrict__ h0, const float* __restrict__ c0,
    const float* __restrict__ Whh, float* __restrict__ out)
{
    extern __shared__ float sm[];
    float* h_s    = sm;            // 16*512       = 8192 floats
    float* xp_s   = sm + 8192;     // 16*64        = 1024
    float* part_s = sm + 9216;     // 16*64*9      = 9216 (pad-9: conflict-free)
    float* c_s    = sm + 18432;    // 16*16        =  256   total 18688 floats

    const int tid  = threadIdx.x;
    const int cq   = tid & 63;           // local gate col
    const int s    = tid >> 6;           // K slice (8 x 64)
    const int gate = cq >> 4;
    const int jj   = cq & 15;
    const int j0   = blockIdx.x * 16;    // h-col base (32 col groups)
    const int B0   = blockIdx.y * 16;    // batch base (4 batch groups)
    const int gcol = gate * HDIM + j0 + jj;
    const unsigned nCTA = gridDim.x * gridDim.y;

    // W_hh[gcol][s*64 .. s*64+63] -> 32 packed f32x2 registers (loaded once)
    unsigned long long w[32];
    {
        const float4* wp = (const float4*)(Whh + (size_t)gcol * HDIM + s * 64);
#pragma unroll
        for (int q = 0; q < 16; q++) {
            float4 v = wp[q];
            w[2 * q]     = pk2(v.x, v.y);
            w[2 * q + 1] = pk2(v.z, v.w);
        }
    }
    if (tid < 256)
        c_s[tid] = c0[(size_t)(B0 + (tid >> 4)) * HDIM + j0 + (tid & 15)];

    for (int t = T_STEPS - 1; t >= 0; t--) {
        // ---- stage h (8KB) and x_proj slice (4KB); overlapped LDG latency ----
        const float* hsrc = (t == T_STEPS - 1)
                              ? (h0 + (size_t)B0 * HDIM)
                              : (out + (size_t)(t + 1) * (BATCH * HDIM)
                                     + (size_t)B0 * HDIM);
        float4 hv0 = ((const float4*)hsrc)[tid];
        float4 hv1 = ((const float4*)hsrc)[tid + 512];
        float4 hv2 = ((const float4*)hsrc)[tid + 1024];
        float4 hv3 = ((const float4*)hsrc)[tid + 1536];
        float4 xv;
        if (tid < 256) {
            int bi = tid >> 4, q = tid & 15;
            int g = q >> 2, f = q & 3;
            xv = *(const float4*)(g_xproj
                    + ((size_t)t * BATCH + B0 + bi) * G4
                    + g * HDIM + j0 + f * 4);
        }
        ((float4*)h_s)[tid]        = hv0;
        ((float4*)h_s)[tid + 512]  = hv1;
        ((float4*)h_s)[tid + 1024] = hv2;
        ((float4*)h_s)[tid + 1536] = hv3;
        if (tid < 256) {
            int bi = tid >> 4, q = tid & 15;
            int g = q >> 2, f = q & 3;
            ((float4*)xp_s)[bi * 16 + g * 4 + f] = xv;
        }
        __syncthreads();

        // ---- phase A: per-thread dot of W regs against broadcast h pairs ----
#pragma unroll 1
        for (int bi = 0; bi < 16; bi++) {
            const ulonglong2* hp =
                (const ulonglong2*)(h_s + bi * HDIM + s * 64);
            unsigned long long a0 = 0ull, a1 = 0ull;
#pragma unroll
            for (int q = 0; q < 16; q++) {
                ulonglong2 hvp = hp[q];          // ld.shared.v2.u64 (broadcast)
                a0 = fma2(hvp.x, w[2 * q],     a0);
                a1 = fma2(hvp.y, w[2 * q + 1], a1);
            }
            float l0, u0, l1, u1;
            upk2(a0, l0, u0); upk2(a1, l1, u1);
            part_s[(bi * 64 + cq) * 9 + s] = (l0 + u0) + (l1 + u1);
        }
        __syncthreads();

        // ---- reduce 8 K-slices + cell update (256 threads) ----
        if (tid < 256) {
            int bi = tid >> 4, j = tid & 15;
            float pre[4];
#pragma unroll
            for (int g = 0; g < 4; g++) {
                const float* pp = part_s + (bi * 64 + g * 16 + j) * 9;
                float r = ((pp[0] + pp[1]) + (pp[2] + pp[3])) +
                          ((pp[4] + pp[5]) + (pp[6] + pp[7]));
                pre[g] = xp_s[bi * 64 + g * 16 + j] + r;
            }
            float gi = sigf(pre[0]);
            float gf = sigf(pre[1]);
            float gz = sigf(pre[2]);
            float go = sigf(pre[3]);
            float cn = gf * c_s[tid] + gz - gi;
            c_s[tid] = cn;
            float hn = sigf(cn) - go;
            out[(size_t)t * (BATCH * HDIM) + (size_t)(B0 + bi) * HDIM + j0 + j] = hn;
            if (t == 0) {
                const size_t base = (size_t)T_STEPS * BATCH * HDIM;
                out[base + (size_t)(B0 + bi) * HDIM + j0 + j] = hn;          // h_f
                out[base + BATCH * HDIM + (size_t)(B0 + bi) * HDIM + j0 + j] = cn; // c_f
            }
            __threadfence();   // publish h before signaling
        }
        __syncthreads();

        // ---- grid barrier (skipped after final step) ----
        if (t > 0) {
            if (tid == 0) {
                atomicAdd(&g_bar, 1u);
                unsigned target = (unsigned)(T_STEPS - t) * nCTA;
                volatile unsigned* p = &g_bar;
                while (*p < target) { }
                __threadfence();
            }
            __syncthreads();
        }
    }

    // ---- self-reset of barrier counters (last arriver) ----
    __syncthreads();
    if (tid == 0) {
        unsigned v = atomicAdd(&g_done, 1u);
        if (v == nCTA - 1u) {
            atomicExch(&g_bar, 0u);
            atomicExch(&g_done, 0u);
        }
    }
}

// ---------------------------------------------------------------------------
extern "C" void kernel_launch(void* const* d_in, const int* in_sizes, int n_in,
                              void* d_out, int out_size)
{
    const float* input = (const float*)d_in[0];
    const float* h0    = (const float*)d_in[1];
    const float* c0    = (const float*)d_in[2];
    const float* Wih   = (const float*)d_in[3];
    const float* Whh   = (const float*)d_in[4];
    const float* bih   = (const float*)d_in[5];
    const float* bhh   = (const float*)d_in[6];
    float* out = (float*)d_out;

    const size_t smem_bytes = 18688 * sizeof(float);   // 74,752 B
    static int configured = 0;
    if (!configured) {
        cudaFuncSetAttribute(recur_kernel,
                             cudaFuncAttributeMaxDynamicSharedMemorySize,
                             (int)smem_bytes);
        configured = 1;
    }

    xproj_kernel<<<dim3(G4 / 128, (T_STEPS * BATCH) / 128), 256>>>(
        input, Wih, bih, bhh);
    recur_kernel<<<dim3(HDIM / 16, BATCH / 16), 512, smem_bytes>>>(
        h0, c0, Whh, out);
}

// round 5
// speedup vs baseline: 1.2610x; 1.1351x over previous
#include <cuda_runtime.h>
#include <cuda_bf16.h>
#include <math.h>
#include <stdint.h>

#define T_STEPS 1024
#define BATCH   64
#define IDIM    512
#define HDIM    512
#define G4      2048   // 4*H
#define MTOT    (T_STEPS * BATCH)   // 65536

// ---- device-global scratch (no allocs allowed) ----
__device__ float        g_xproj[(size_t)MTOT * G4];   // 512 MB
__device__ unsigned int g_bar;
__device__ unsigned int g_done;

// ---------------- f32x2 packed-FMA helpers ----------------
__device__ __forceinline__ unsigned long long pk2(float lo, float hi) {
    unsigned long long r;
    asm("mov.b64 %0, {%1, %2};" : "=l"(r) : "f"(lo), "f"(hi));
    return r;
}
__device__ __forceinline__ void upk2(unsigned long long v, float& lo, float& hi) {
    asm("mov.b64 {%0, %1}, %2;" : "=f"(lo), "=f"(hi) : "l"(v));
}
__device__ __forceinline__ unsigned long long fma2(unsigned long long a,
                                                   unsigned long long b,
                                                   unsigned long long c) {
    unsigned long long d;
    asm("fma.rn.f32x2 %0, %1, %2, %3;" : "=l"(d) : "l"(a), "l"(b), "l"(c));
    return d;
}
__device__ __forceinline__ float sigf(float x) {
    return 1.0f / (1.0f + expf(-x));
}

// ---------------- mma.sync helpers (baseline PTX, no 'a' features) ----------
__device__ __forceinline__ uint32_t smem_u32(const void* p) {
    uint32_t a;
    asm("{ .reg .u64 t; cvta.to.shared.u64 t, %1; cvt.u32.u64 %0, t; }"
        : "=r"(a) : "l"(p));
    return a;
}
__device__ __forceinline__ void ldm4(uint32_t* r, uint32_t addr) {
    asm volatile("ldmatrix.sync.aligned.m8n8.x4.shared.b16 {%0,%1,%2,%3}, [%4];"
                 : "=r"(r[0]), "=r"(r[1]), "=r"(r[2]), "=r"(r[3]) : "r"(addr));
}
__device__ __forceinline__ void mma16816(float* d, const uint32_t* a,
                                         uint32_t b0, uint32_t b1) {
    asm volatile(
        "mma.sync.aligned.m16n8k16.row.col.f32.bf16.bf16.f32 "
        "{%0,%1,%2,%3}, {%4,%5,%6,%7}, {%8,%9}, {%0,%1,%2,%3};"
        : "+f"(d[0]), "+f"(d[1]), "+f"(d[2]), "+f"(d[3])
        : "r"(a[0]), "r"(a[1]), "r"(a[2]), "r"(a[3]), "r"(b0), "r"(b1));
}
// split one fp32x4 into packed bf16 hi-pair / lo-pair words
__device__ __forceinline__ void split4(const float4 v, uint2& hi, uint2& lo) {
    __nv_bfloat16 h0 = __float2bfloat16(v.x), h1 = __float2bfloat16(v.y);
    __nv_bfloat16 h2 = __float2bfloat16(v.z), h3 = __float2bfloat16(v.w);
    __nv_bfloat16 l0 = __float2bfloat16(v.x - __bfloat162float(h0));
    __nv_bfloat16 l1 = __float2bfloat16(v.y - __bfloat162float(h1));
    __nv_bfloat16 l2 = __float2bfloat16(v.z - __bfloat162float(h2));
    __nv_bfloat16 l3 = __float2bfloat16(v.w - __bfloat162float(h3));
    hi.x = (uint32_t)__bfloat16_as_ushort(h0) |
           ((uint32_t)__bfloat16_as_ushort(h1) << 16);
    hi.y = (uint32_t)__bfloat16_as_ushort(h2) |
           ((uint32_t)__bfloat16_as_ushort(h3) << 16);
    lo.x = (uint32_t)__bfloat16_as_ushort(l0) |
           ((uint32_t)__bfloat16_as_ushort(l1) << 16);
    lo.y = (uint32_t)__bfloat16_as_ushort(l2) |
           ((uint32_t)__bfloat16_as_ushort(l3) << 16);
}

// ---------------------------------------------------------------------------
// Kernel 1: x_proj = input @ W_ih^T + b_ih + b_hh  via bf16 hi/lo-split HMMA.
// M=65536, N=2048, K=512. CTA tile 128x128; 8 warps in 4(M)x2(N), warp tile
// 32x64. K in 16 chunks of 32; per chunk: Ah*Wh + Ah*Wl + Al*Wh into one fp32
// accumulator. fp32->bf16 split happens in registers during staging.
// SMEM rows padded to 80B -> conflict-free ldmatrix.
// ---------------------------------------------------------------------------
#define XS_ROW   80                       // bytes per smem row (32 bf16 + pad)
#define XS_BUF   (128 * XS_ROW)           // 10240 B per tile buffer
__global__ void __launch_bounds__(256, 1) xproj_mma_kernel(
    const float* __restrict__ A, const float* __restrict__ W,
    const float* __restrict__ bih, const float* __restrict__ bhh)
{
    __shared__ __align__(16) char sAH[XS_BUF];
    __shared__ __align__(16) char sAL[XS_BUF];
    __shared__ __align__(16) char sWH[XS_BUF];
    __shared__ __align__(16) char sWL[XS_BUF];
    __shared__ float sBias[128];

    const int tid = threadIdx.x;
    const int n0 = blockIdx.x * 128;
    const int m0 = blockIdx.y * 128;
    const int lane = tid & 31, wid = tid >> 5;
    const int wm = wid >> 1, wn = wid & 1;

    if (tid < 128) sBias[tid] = bih[n0 + tid] + bhh[n0 + tid];

    // staging map: idx = tid + i*256 (i<4); row = idx>>3, c4 = (idx&7)*4
    const int srow = tid >> 3;
    const int sc4  = (tid & 7) << 2;
    const float* agp = A + (size_t)(m0 + srow) * IDIM + sc4;
    const float* wgp = W + (size_t)(n0 + srow) * IDIM + sc4;

    // ldmatrix lane addressing
    const int lr = lane & 7, sel = lane >> 3;
    const int koff2 = ((sel >> 1) * 8) * 2;           // byte offset of k-half
    const uint32_t aH = smem_u32(sAH) + (uint32_t)(wm * 32 + (sel & 1) * 8 + lr) * XS_ROW + koff2;
    const uint32_t aL = smem_u32(sAL) + (uint32_t)(wm * 32 + (sel & 1) * 8 + lr) * XS_ROW + koff2;
    const uint32_t bH = smem_u32(sWH) + (uint32_t)(wn * 64 + (sel & 1) * 8 + lr) * XS_ROW + koff2;
    const uint32_t bL = smem_u32(sWL) + (uint32_t)(wn * 64 + (sel & 1) * 8 + lr) * XS_ROW + koff2;

    float d[2][8][4];
#pragma unroll
    for (int i = 0; i < 2; i++)
#pragma unroll
        for (int j = 0; j < 8; j++)
#pragma unroll
            for (int q = 0; q < 4; q++) d[i][j][q] = 0.0f;

    float4 pfA[4], pfW[4];
#pragma unroll
    for (int i = 0; i < 4; i++) {               // prefetch chunk 0
        pfA[i] = *(const float4*)(agp + i * 32 * IDIM);
        pfW[i] = *(const float4*)(wgp + i * 32 * IDIM);
    }

    for (int kc = 0; kc < 16; kc++) {
        // ---- split + store staged chunk ----
#pragma unroll
        for (int i = 0; i < 4; i++) {
            int row = srow + i * 32;
            uint2 hi, lo;
            split4(pfA[i], hi, lo);
            *(uint2*)(sAH + row * XS_ROW + sc4 * 2) = hi;
            *(uint2*)(sAL + row * XS_ROW + sc4 * 2) = lo;
            split4(pfW[i], hi, lo);
            *(uint2*)(sWH + row * XS_ROW + sc4 * 2) = hi;
            *(uint2*)(sWL + row * XS_ROW + sc4 * 2) = lo;
        }
        __syncthreads();

        if (kc < 15) {                           // prefetch next chunk
            const float* an = agp + (kc + 1) * 32;
            const float* wnp = wgp + (kc + 1) * 32;
#pragma unroll
            for (int i = 0; i < 4; i++) {
                pfA[i] = *(const float4*)(an + i * 32 * IDIM);
                pfW[i] = *(const float4*)(wnp + i * 32 * IDIM);
            }
        }

        // ---- compute: 2 k16 steps x 3 split terms ----
#pragma unroll
        for (int k16 = 0; k16 < 2; k16++) {
            const uint32_t ko = (uint32_t)(k16 * 32);
            uint32_t ah[2][4], al[2][4];
            ldm4(ah[0], aH + ko);
            ldm4(ah[1], aH + ko + 16 * XS_ROW);
            ldm4(al[0], aL + ko);
            ldm4(al[1], aL + ko + 16 * XS_ROW);
#pragma unroll
            for (int bnp = 0; bnp < 4; bnp++) {
                uint32_t bh[4], bl[4];
                ldm4(bh, bH + ko + (uint32_t)(bnp * 16) * XS_ROW);
                mma16816(d[0][2 * bnp],     ah[0], bh[0], bh[2]);
                mma16816(d[0][2 * bnp + 1], ah[0], bh[1], bh[3]);
                mma16816(d[1][2 * bnp],     ah[1], bh[0], bh[2]);
                mma16816(d[1][2 * bnp + 1], ah[1], bh[1], bh[3]);
                mma16816(d[0][2 * bnp],     al[0], bh[0], bh[2]);
                mma16816(d[0][2 * bnp + 1], al[0], bh[1], bh[3]);
                mma16816(d[1][2 * bnp],     al[1], bh[0], bh[2]);
                mma16816(d[1][2 * bnp + 1], al[1], bh[1], bh[3]);
                ldm4(bl, bL + ko + (uint32_t)(bnp * 16) * XS_ROW);
                mma16816(d[0][2 * bnp],     ah[0], bl[0], bl[2]);
                mma16816(d[0][2 * bnp + 1], ah[0], bl[1], bl[3]);
                mma16816(d[1][2 * bnp],     ah[1], bl[0], bl[2]);
                mma16816(d[1][2 * bnp + 1], ah[1], bl[1], bl[3]);
            }
        }
        __syncthreads();
    }

    // ---- epilogue: bias + fp32 store ----
    const int erow = m0 + wm * 32 + (lane >> 2);
    const int ecol = wn * 64 + (lane & 3) * 2;
#pragma unroll
    for (int am = 0; am < 2; am++) {
#pragma unroll
        for (int bn = 0; bn < 8; bn++) {
            int col = ecol + bn * 8;
            float b0 = sBias[col], b1 = sBias[col + 1];
            float* p0 = g_xproj + (size_t)(erow + am * 16) * G4 + n0 + col;
            float* p1 = p0 + 8 * G4;
            float2 v0 = make_float2(d[am][bn][0] + b0, d[am][bn][1] + b1);
            float2 v1 = make_float2(d[am][bn][2] + b0, d[am][bn][3] + b1);
            *(float2*)p0 = v0;
            *(float2*)p1 = v1;
        }
    }
}

// ---------------------------------------------------------------------------
// Kernel 2: persistent reverse-scan recurrence (UNCHANGED, passing).
// ---------------------------------------------------------------------------
__global__ void __launch_bounds__(512, 1) recur_kernel(
    const float* __restrict__ h0, const float* __restrict__ c0,
    const float* __restrict__ Whh, float* __restrict__ out)
{
    extern __shared__ float sm[];
    float* h_s    = sm;            // 16*512 = 8192
    float* xp_s   = sm + 8192;     // 1024
    float* part_s = sm + 9216;     // 16*64*9 = 9216
    float* c_s    = sm + 18432;    // 256    total 18688

    const int tid  = threadIdx.x;
    const int cq   = tid & 63;
    const int s    = tid >> 6;
    const int gate = cq >> 4;
    const int jj   = cq & 15;
    const int j0   = blockIdx.x * 16;
    const int B0   = blockIdx.y * 16;
    const int gcol = gate * HDIM + j0 + jj;
    const unsigned nCTA = gridDim.x * gridDim.y;

    unsigned long long w[32];
    {
        const float4* wp = (const float4*)(Whh + (size_t)gcol * HDIM + s * 64);
#pragma unroll
        for (int q = 0; q < 16; q++) {
            float4 v = wp[q];
            w[2 * q]     = pk2(v.x, v.y);
            w[2 * q + 1] = pk2(v.z, v.w);
        }
    }
    if (tid < 256)
        c_s[tid] = c0[(size_t)(B0 + (tid >> 4)) * HDIM + j0 + (tid & 15)];

    for (int t = T_STEPS - 1; t >= 0; t--) {
        const float* hsrc = (t == T_STEPS - 1)
                              ? (h0 + (size_t)B0 * HDIM)
                              : (out + (size_t)(t + 1) * (BATCH * HDIM)
                                     + (size_t)B0 * HDIM);
        float4 hv0 = ((const float4*)hsrc)[tid];
        float4 hv1 = ((const float4*)hsrc)[tid + 512];
        float4 hv2 = ((const float4*)hsrc)[tid + 1024];
        float4 hv3 = ((const float4*)hsrc)[tid + 1536];
        float4 xv;
        if (tid < 256) {
            int bi = tid >> 4, q = tid & 15;
            int g = q >> 2, f = q & 3;
            xv = *(const float4*)(g_xproj
                    + ((size_t)t * BATCH + B0 + bi) * G4
                    + g * HDIM + j0 + f * 4);
        }
        ((float4*)h_s)[tid]        = hv0;
        ((float4*)h_s)[tid + 512]  = hv1;
        ((float4*)h_s)[tid + 1024] = hv2;
        ((float4*)h_s)[tid + 1536] = hv3;
        if (tid < 256) {
            int bi = tid >> 4, q = tid & 15;
            int g = q >> 2, f = q & 3;
            ((float4*)xp_s)[bi * 16 + g * 4 + f] = xv;
        }
        __syncthreads();

#pragma unroll 1
        for (int bi = 0; bi < 16; bi++) {
            const ulonglong2* hp =
                (const ulonglong2*)(h_s + bi * HDIM + s * 64);
            unsigned long long a0 = 0ull, a1 = 0ull;
#pragma unroll
            for (int q = 0; q < 16; q++) {
                ulonglong2 hvp = hp[q];
                a0 = fma2(hvp.x, w[2 * q],     a0);
                a1 = fma2(hvp.y, w[2 * q + 1], a1);
            }
            float l0, u0, l1, u1;
            upk2(a0, l0, u0); upk2(a1, l1, u1);
            part_s[(bi * 64 + cq) * 9 + s] = (l0 + u0) + (l1 + u1);
        }
        __syncthreads();

        if (tid < 256) {
            int bi = tid >> 4, j = tid & 15;
            float pre[4];
#pragma unroll
            for (int g = 0; g < 4; g++) {
                const float* pp = part_s + (bi * 64 + g * 16 + j) * 9;
                float r = ((pp[0] + pp[1]) + (pp[2] + pp[3])) +
                          ((pp[4] + pp[5]) + (pp[6] + pp[7]));
                pre[g] = xp_s[bi * 64 + g * 16 + j] + r;
            }
            float gi = sigf(pre[0]);
            float gf = sigf(pre[1]);
            float gz = sigf(pre[2]);
            float go = sigf(pre[3]);
            float cn = gf * c_s[tid] + gz - gi;
            c_s[tid] = cn;
            float hn = sigf(cn) - go;
            out[(size_t)t * (BATCH * HDIM) + (size_t)(B0 + bi) * HDIM + j0 + j] = hn;
            if (t == 0) {
                const size_t base = (size_t)T_STEPS * BATCH * HDIM;
                out[base + (size_t)(B0 + bi) * HDIM + j0 + j] = hn;
                out[base + BATCH * HDIM + (size_t)(B0 + bi) * HDIM + j0 + j] = cn;
            }
            __threadfence();
        }
        __syncthreads();

        if (t > 0) {
            if (tid == 0) {
                atomicAdd(&g_bar, 1u);
                unsigned target = (unsigned)(T_STEPS - t) * nCTA;
                volatile unsigned* p = &g_bar;
                while (*p < target) { }
                __threadfence();
            }
            __syncthreads();
        }
    }

    __syncthreads();
    if (tid == 0) {
        unsigned v = atomicAdd(&g_done, 1u);
        if (v == nCTA - 1u) {
            atomicExch(&g_bar, 0u);
            atomicExch(&g_done, 0u);
        }
    }
}

// ---------------------------------------------------------------------------
extern "C" void kernel_launch(void* const* d_in, const int* in_sizes, int n_in,
                              void* d_out, int out_size)
{
    const float* input = (const float*)d_in[0];
    const float* h0    = (const float*)d_in[1];
    const float* c0    = (const float*)d_in[2];
    const float* Wih   = (const float*)d_in[3];
    const float* Whh   = (const float*)d_in[4];
    const float* bih   = (const float*)d_in[5];
    const float* bhh   = (const float*)d_in[6];
    float* out = (float*)d_out;

    const size_t recur_smem = 18688 * sizeof(float);   // 74,752 B
    static int configured = 0;
    if (!configured) {
        cudaFuncSetAttribute(recur_kernel,
                             cudaFuncAttributeMaxDynamicSharedMemorySize,
                             (int)recur_smem);
        configured = 1;
    }

    xproj_mma_kernel<<<dim3(G4 / 128, MTOT / 128), 256>>>(input, Wih, bih, bhh);
    recur_kernel<<<dim3(HDIM / 16, BATCH / 16), 512, recur_smem>>>(
        h0, c0, Whh, out);
}

// round 6
// speedup vs baseline: 1.6342x; 1.2959x over previous
#include <cuda_runtime.h>
#include <cuda_bf16.h>
#include <math.h>
#include <stdint.h>

#define T_STEPS 1024
#define BATCH   64
#define IDIM    512
#define HDIM    512
#define G4      2048   // 4*H
#define MTOT    (T_STEPS * BATCH)   // 65536

// ---- device-global scratch (no allocs allowed) ----
__device__ float        g_xproj[(size_t)MTOT * G4];   // 512 MB
__device__ unsigned int g_bar4[4 * 32];               // per-batch-group counters
__device__ unsigned int g_done;

__device__ __forceinline__ float sigf(float x) {
    return 1.0f / (1.0f + expf(-x));
}

// ---------------- mma.sync helpers (baseline PTX, no 'a' features) ----------
__device__ __forceinline__ uint32_t smem_u32(const void* p) {
    uint32_t a;
    asm("{ .reg .u64 t; cvta.to.shared.u64 t, %1; cvt.u32.u64 %0, t; }"
        : "=r"(a) : "l"(p));
    return a;
}
__device__ __forceinline__ void ldm4(uint32_t* r, uint32_t addr) {
    asm volatile("ldmatrix.sync.aligned.m8n8.x4.shared.b16 {%0,%1,%2,%3}, [%4];"
                 : "=r"(r[0]), "=r"(r[1]), "=r"(r[2]), "=r"(r[3]) : "r"(addr));
}
__device__ __forceinline__ void ldm2(uint32_t* r, uint32_t addr) {
    asm volatile("ldmatrix.sync.aligned.m8n8.x2.shared.b16 {%0,%1}, [%2];"
                 : "=r"(r[0]), "=r"(r[1]) : "r"(addr));
}
__device__ __forceinline__ void mma16816(float* d, const uint32_t* a,
                                         uint32_t b0, uint32_t b1) {
    asm volatile(
        "mma.sync.aligned.m16n8k16.row.col.f32.bf16.bf16.f32 "
        "{%0,%1,%2,%3}, {%4,%5,%6,%7}, {%8,%9}, {%0,%1,%2,%3};"
        : "+f"(d[0]), "+f"(d[1]), "+f"(d[2]), "+f"(d[3])
        : "r"(a[0]), "r"(a[1]), "r"(a[2]), "r"(a[3]), "r"(b0), "r"(b1));
}
// split one fp32x4 into packed bf16 hi-pair / lo-pair words
__device__ __forceinline__ void split4(const float4 v, uint2& hi, uint2& lo) {
    __nv_bfloat16 h0 = __float2bfloat16(v.x), h1 = __float2bfloat16(v.y);
    __nv_bfloat16 h2 = __float2bfloat16(v.z), h3 = __float2bfloat16(v.w);
    __nv_bfloat16 l0 = __float2bfloat16(v.x - __bfloat162float(h0));
    __nv_bfloat16 l1 = __float2bfloat16(v.y - __bfloat162float(h1));
    __nv_bfloat16 l2 = __float2bfloat16(v.z - __bfloat162float(h2));
    __nv_bfloat16 l3 = __float2bfloat16(v.w - __bfloat162float(h3));
    hi.x = (uint32_t)__bfloat16_as_ushort(h0) |
           ((uint32_t)__bfloat16_as_ushort(h1) << 16);
    hi.y = (uint32_t)__bfloat16_as_ushort(h2) |
           ((uint32_t)__bfloat16_as_ushort(h3) << 16);
    lo.x = (uint32_t)__bfloat16_as_ushort(l0) |
           ((uint32_t)__bfloat16_as_ushort(l1) << 16);
    lo.y = (uint32_t)__bfloat16_as_ushort(l2) |
           ((uint32_t)__bfloat16_as_ushort(l3) << 16);
}

// ---------------------------------------------------------------------------
// Kernel 1: x_proj via bf16 hi/lo-split HMMA (UNCHANGED from round 5, passing)
// ---------------------------------------------------------------------------
#define XS_ROW   80
#define XS_BUF   (128 * XS_ROW)
__global__ void __launch_bounds__(256, 1) xproj_mma_kernel(
    const float* __restrict__ A, const float* __restrict__ W,
    const float* __restrict__ bih, const float* __restrict__ bhh)
{
    __shared__ __align__(16) char sAH[XS_BUF];
    __shared__ __align__(16) char sAL[XS_BUF];
    __shared__ __align__(16) char sWH[XS_BUF];
    __shared__ __align__(16) char sWL[XS_BUF];
    __shared__ float sBias[128];

    const int tid = threadIdx.x;
    const int n0 = blockIdx.x * 128;
    const int m0 = blockIdx.y * 128;
    const int lane = tid & 31, wid = tid >> 5;
    const int wm = wid >> 1, wn = wid & 1;

    if (tid < 128) sBias[tid] = bih[n0 + tid] + bhh[n0 + tid];

    const int srow = tid >> 3;
    const int sc4  = (tid & 7) << 2;
    const float* agp = A + (size_t)(m0 + srow) * IDIM + sc4;
    const float* wgp = W + (size_t)(n0 + srow) * IDIM + sc4;

    const int lr = lane & 7, sel = lane >> 3;
    const int koff2 = ((sel >> 1) * 8) * 2;
    const uint32_t aH = smem_u32(sAH) + (uint32_t)(wm * 32 + (sel & 1) * 8 + lr) * XS_ROW + koff2;
    const uint32_t aL = smem_u32(sAL) + (uint32_t)(wm * 32 + (sel & 1) * 8 + lr) * XS_ROW + koff2;
    const uint32_t bH = smem_u32(sWH) + (uint32_t)(wn * 64 + (sel & 1) * 8 + lr) * XS_ROW + koff2;
    const uint32_t bL = smem_u32(sWL) + (uint32_t)(wn * 64 + (sel & 1) * 8 + lr) * XS_ROW + koff2;

    float d[2][8][4];
#pragma unroll
    for (int i = 0; i < 2; i++)
#pragma unroll
        for (int j = 0; j < 8; j++)
#pragma unroll
            for (int q = 0; q < 4; q++) d[i][j][q] = 0.0f;

    float4 pfA[4], pfW[4];
#pragma unroll
    for (int i = 0; i < 4; i++) {
        pfA[i] = *(const float4*)(agp + i * 32 * IDIM);
        pfW[i] = *(const float4*)(wgp + i * 32 * IDIM);
    }

    for (int kc = 0; kc < 16; kc++) {
#pragma unroll
        for (int i = 0; i < 4; i++) {
            int row = srow + i * 32;
            uint2 hi, lo;
            split4(pfA[i], hi, lo);
            *(uint2*)(sAH + row * XS_ROW + sc4 * 2) = hi;
            *(uint2*)(sAL + row * XS_ROW + sc4 * 2) = lo;
            split4(pfW[i], hi, lo);
            *(uint2*)(sWH + row * XS_ROW + sc4 * 2) = hi;
            *(uint2*)(sWL + row * XS_ROW + sc4 * 2) = lo;
        }
        __syncthreads();

        if (kc < 15) {
            const float* an = agp + (kc + 1) * 32;
            const float* wnp = wgp + (kc + 1) * 32;
#pragma unroll
            for (int i = 0; i < 4; i++) {
                pfA[i] = *(const float4*)(an + i * 32 * IDIM);
                pfW[i] = *(const float4*)(wnp + i * 32 * IDIM);
            }
        }

#pragma unroll
        for (int k16 = 0; k16 < 2; k16++) {
            const uint32_t ko = (uint32_t)(k16 * 32);
            uint32_t ah[2][4], al[2][4];
            ldm4(ah[0], aH + ko);
            ldm4(ah[1], aH + ko + 16 * XS_ROW);
            ldm4(al[0], aL + ko);
            ldm4(al[1], aL + ko + 16 * XS_ROW);
#pragma unroll
            for (int bnp = 0; bnp < 4; bnp++) {
                uint32_t bh[4], bl[4];
                ldm4(bh, bH + ko + (uint32_t)(bnp * 16) * XS_ROW);
                mma16816(d[0][2 * bnp],     ah[0], bh[0], bh[2]);
                mma16816(d[0][2 * bnp + 1], ah[0], bh[1], bh[3]);
                mma16816(d[1][2 * bnp],     ah[1], bh[0], bh[2]);
                mma16816(d[1][2 * bnp + 1], ah[1], bh[1], bh[3]);
                mma16816(d[0][2 * bnp],     al[0], bh[0], bh[2]);
                mma16816(d[0][2 * bnp + 1], al[0], bh[1], bh[3]);
                mma16816(d[1][2 * bnp],     al[1], bh[0], bh[2]);
                mma16816(d[1][2 * bnp + 1], al[1], bh[1], bh[3]);
                ldm4(bl, bL + ko + (uint32_t)(bnp * 16) * XS_ROW);
                mma16816(d[0][2 * bnp],     ah[0], bl[0], bl[2]);
                mma16816(d[0][2 * bnp + 1], ah[0], bl[1], bl[3]);
                mma16816(d[1][2 * bnp],     ah[1], bl[0], bl[2]);
                mma16816(d[1][2 * bnp + 1], ah[1], bl[1], bl[3]);
            }
        }
        __syncthreads();
    }

    const int erow = m0 + wm * 32 + (lane >> 2);
    const int ecol = wn * 64 + (lane & 3) * 2;
#pragma unroll
    for (int am = 0; am < 2; am++) {
#pragma unroll
        for (int bn = 0; bn < 8; bn++) {
            int col = ecol + bn * 8;
            float b0 = sBias[col], b1 = sBias[col + 1];
            float* p0 = g_xproj + (size_t)(erow + am * 16) * G4 + n0 + col;
            float* p1 = p0 + 8 * G4;
            *(float2*)p0 = make_float2(d[am][bn][0] + b0, d[am][bn][1] + b1);
            *(float2*)p1 = make_float2(d[am][bn][2] + b0, d[am][bn][3] + b1);
        }
    }
}

// ---------------------------------------------------------------------------
// Kernel 2: persistent reverse-scan recurrence via HMMA bf16 hi/lo split.
// Grid (32 col-groups, 4 batch-groups). CTA: 16 batches x 16 h-cols
// (64 gate cols, gate-major rows: row = gate*16 + jj).
// W_hh slice in SMEM as bf16 hi/lo (converted once). Per step: stage h fp32 ->
// bf16 hi/lo, 16 warps = (kw in 2 K-halves) x (nw in 8 n-slices) compute
// [16 x 8] each via 48 MMAs, partial-reduce in SMEM, 256 threads do cell.
// Barrier is per-batch-group (32 CTA fan-in).
// ---------------------------------------------------------------------------
#define R_STRIDE 520                       // bf16 elems per smem row (1040 B)
#define OFF_WHI  0
#define OFF_WLO  66560
#define OFF_HHI  133120
#define OFF_HLO  149760
#define OFF_XP   166400                    // float [16][64]
#define OFF_PRE  170496                    // float [2][16][72]
#define OFF_C    179712                    // float [256]
#define R_SMEM   180736

__global__ void __launch_bounds__(512, 1) recur_mma_kernel(
    const float* __restrict__ h0, const float* __restrict__ c0,
    const float* __restrict__ Whh, float* __restrict__ out)
{
    extern __shared__ char sm[];
    float* xp_s  = (float*)(sm + OFF_XP);
    float* pre_s = (float*)(sm + OFF_PRE);
    float* c_s   = (float*)(sm + OFF_C);

    const int tid  = threadIdx.x;
    const int lane = tid & 31, wid = tid >> 5;
    const int kw = wid >> 3;               // K half (0/1)
    const int nw = wid & 7;                // n-slice of 8 gate cols
    const int j0 = blockIdx.x * 16;
    const int B0 = blockIdx.y * 16;
    const int grp = blockIdx.y;

    // ---- convert W_hh slice to bf16 hi/lo in SMEM (once) ----
#pragma unroll 4
    for (int i = 0; i < 16; i++) {
        int idx = tid + i * 512;           // 0..8191 float4 chunks
        int row = idx >> 7;                // 0..63 (gate*16 + jj)
        int f4  = (idx & 127) << 2;        // col 0..508 step 4
        int gate = row >> 4, jj = row & 15;
        float4 v = *(const float4*)(Whh
                      + (size_t)(gate * HDIM + j0 + jj) * HDIM + f4);
        uint2 hi, lo;
        split4(v, hi, lo);
        *(uint2*)(sm + OFF_WHI + row * 1040 + f4 * 2) = hi;
        *(uint2*)(sm + OFF_WLO + row * 1040 + f4 * 2) = lo;
    }
    if (tid < 256)
        c_s[tid] = c0[(size_t)(B0 + (tid >> 4)) * HDIM + j0 + (tid & 15)];

    // ---- ldmatrix lane addressing ----
    const int lr = lane & 7, sel = lane >> 3;
    const uint32_t aRowOff = (uint32_t)((sel & 1) * 8 + lr) * 1040u
                           + (uint32_t)(sel >> 1) * 16u;
    const uint32_t aHiB = smem_u32(sm + OFF_HHI) + aRowOff;
    const uint32_t aLoB = smem_u32(sm + OFF_HLO) + aRowOff;
    const int bl_ = lane & 15;
    const uint32_t bRowOff = (uint32_t)(nw * 8 + (bl_ & 7)) * 1040u
                           + (uint32_t)(bl_ >> 3) * 16u;
    const uint32_t bHiB = smem_u32(sm + OFF_WHI) + bRowOff;
    const uint32_t bLoB = smem_u32(sm + OFF_WLO) + bRowOff;
    const uint32_t kbB = (uint32_t)(kw * 256 * 2);   // K-half byte offset

    __syncthreads();

    for (int t = T_STEPS - 1; t >= 0; t--) {
        // ---- stage h fp32 -> bf16 hi/lo (512 thr), xp (256 thr) ----
        const float* hsrc = (t == T_STEPS - 1)
                              ? (h0 + (size_t)B0 * HDIM)
                              : (out + (size_t)(t + 1) * (BATCH * HDIM)
                                     + (size_t)B0 * HDIM);
        {
            int r  = tid & 15;
            int cb = (tid >> 4) * 16;
            const float4* hp = (const float4*)(hsrc + r * HDIM + cb);
            float4 v0 = hp[0], v1 = hp[1], v2 = hp[2], v3 = hp[3];
            float4 xv;
            if (tid < 256) {
                int b = tid >> 4, q = tid & 15;
                int g = q >> 2, f = q & 3;
                xv = *(const float4*)(g_xproj
                        + ((size_t)t * BATCH + B0 + b) * G4
                        + g * HDIM + j0 + f * 4);
            }
            char* dH = sm + OFF_HHI + r * 1040 + cb * 2;
            char* dL = sm + OFF_HLO + r * 1040 + cb * 2;
            uint2 hi, lo;
            split4(v0, hi, lo); *(uint2*)(dH) = hi;      *(uint2*)(dL) = lo;
            split4(v1, hi, lo); *(uint2*)(dH + 8) = hi;  *(uint2*)(dL + 8) = lo;
            split4(v2, hi, lo); *(uint2*)(dH + 16) = hi; *(uint2*)(dL + 16) = lo;
            split4(v3, hi, lo); *(uint2*)(dH + 24) = hi; *(uint2*)(dL + 24) = lo;
            if (tid < 256) {
                int b = tid >> 4, q = tid & 15;
                int g = q >> 2, f = q & 3;
                *(float4*)(xp_s + b * 64 + g * 16 + f * 4) = xv;
            }
        }
        __syncthreads();

        // ---- MMA: 16 k-steps x (AhWh, AlWh, AhWl) ----
        float dA[4] = {0.f, 0.f, 0.f, 0.f};
        float dB[4] = {0.f, 0.f, 0.f, 0.f};
#pragma unroll
        for (int ks = 0; ks < 16; ks++) {
            uint32_t ko = kbB + (uint32_t)(ks * 32);
            uint32_t ah[4], al[4], bh[2], bl2[2];
            ldm4(ah, aHiB + ko);
            ldm4(al, aLoB + ko);
            ldm2(bh, bHiB + ko);
            ldm2(bl2, bLoB + ko);
            mma16816(dA, ah, bh[0], bh[1]);
            mma16816(dB, al, bh[0], bh[1]);
            mma16816(dA, ah, bl2[0], bl2[1]);
        }
        // ---- write per-K-half partials: pre_s[kw][16][72] ----
        {
            int r = lane >> 2;
            int c = nw * 8 + (lane & 3) * 2;
            float* p = pre_s + kw * 1152 + r * 72 + c;
            *(float2*)p           = make_float2(dA[0] + dB[0], dA[1] + dB[1]);
            *(float2*)(p + 8*72)  = make_float2(dA[2] + dB[2], dA[3] + dB[3]);
        }
        __syncthreads();

        // ---- reduce K-halves + cell update (256 threads) ----
        if (tid < 256) {
            int b = tid >> 4, jj = tid & 15;
            float pre[4];
#pragma unroll
            for (int g = 0; g < 4; g++) {
                int cc = g * 16 + jj;
                pre[g] = pre_s[b * 72 + cc] + pre_s[1152 + b * 72 + cc]
                       + xp_s[b * 64 + cc];
            }
            float gi = sigf(pre[0]);
            float gf = sigf(pre[1]);
            float gz = sigf(pre[2]);
            float go = sigf(pre[3]);
            float cn = gf * c_s[tid] + gz - gi;
            c_s[tid] = cn;
            float hn = sigf(cn) - go;
            out[(size_t)t * (BATCH * HDIM) + (size_t)(B0 + b) * HDIM + j0 + jj] = hn;
            if (t == 0) {
                const size_t base = (size_t)T_STEPS * BATCH * HDIM;
                out[base + (size_t)(B0 + b) * HDIM + j0 + jj] = hn;
                out[base + BATCH * HDIM + (size_t)(B0 + b) * HDIM + j0 + jj] = cn;
            }
            __threadfence();
        }
        __syncthreads();

        // ---- per-batch-group barrier (32 CTAs) ----
        if (t > 0) {
            if (tid == 0) {
                atomicAdd(&g_bar4[grp * 32], 1u);
                unsigned target = (unsigned)(T_STEPS - t) * 32u;
                volatile unsigned* p = &g_bar4[grp * 32];
                while (*p < target) { }
                __threadfence();
            }
            __syncthreads();
        }
    }

    // ---- self-reset of counters (after ALL 128 CTAs finish) ----
    __syncthreads();
    if (tid == 0) {
        unsigned v = atomicAdd(&g_done, 1u);
        if (v == 127u) {
            atomicExch(&g_bar4[0], 0u);
            atomicExch(&g_bar4[32], 0u);
            atomicExch(&g_bar4[64], 0u);
            atomicExch(&g_bar4[96], 0u);
            atomicExch(&g_done, 0u);
        }
    }
}

// ---------------------------------------------------------------------------
extern "C" void kernel_launch(void* const* d_in, const int* in_sizes, int n_in,
                              void* d_out, int out_size)
{
    const float* input = (const float*)d_in[0];
    const float* h0    = (const float*)d_in[1];
    const float* c0    = (const float*)d_in[2];
    const float* Wih   = (const float*)d_in[3];
    const float* Whh   = (const float*)d_in[4];
    const float* bih   = (const float*)d_in[5];
    const float* bhh   = (const float*)d_in[6];
    float* out = (float*)d_out;

    static int configured = 0;
    if (!configured) {
        cudaFuncSetAttribute(recur_mma_kernel,
                             cudaFuncAttributeMaxDynamicSharedMemorySize,
                             R_SMEM);
        configured = 1;
    }

    xproj_mma_kernel<<<dim3(G4 / 128, MTOT / 128), 256>>>(input, Wih, bih, bhh);
    recur_mma_kernel<<<dim3(HDIM / 16, BATCH / 16), 512, R_SMEM>>>(
        h0, c0, Whh, out);
}

// round 8
// speedup vs baseline: 1.7340x; 1.0610x over previous
#include <cuda_runtime.h>
#include <cuda_bf16.h>
#include <math.h>
#include <stdint.h>

#define T_STEPS 1024
#define BATCH   64
#define IDIM    512
#define HDIM    512
#define G4      2048   // 4*H
#define MTOT    (T_STEPS * BATCH)   // 65536

// ---- device-global scratch (no allocs allowed) ----
__device__ float        g_xproj[(size_t)MTOT * G4];   // 512 MB
__device__ unsigned int g_bar4[4 * 32];               // per-batch-group flags
__device__ unsigned int g_done;

__device__ __forceinline__ float sigf(float x) {
    return __fdividef(1.0f, 1.0f + __expf(-x));
}

// ---------------- mma.sync helpers (baseline PTX, no 'a' features) ----------
__device__ __forceinline__ uint32_t smem_u32(const void* p) {
    uint32_t a;
    asm("{ .reg .u64 t; cvta.to.shared.u64 t, %1; cvt.u32.u64 %0, t; }"
        : "=r"(a) : "l"(p));
    return a;
}
__device__ __forceinline__ void ldm4(uint32_t* r, uint32_t addr) {
    asm volatile("ldmatrix.sync.aligned.m8n8.x4.shared.b16 {%0,%1,%2,%3}, [%4];"
                 : "=r"(r[0]), "=r"(r[1]), "=r"(r[2]), "=r"(r[3]) : "r"(addr));
}
__device__ __forceinline__ void mma16816(float* d, const uint32_t* a,
                                         uint32_t b0, uint32_t b1) {
    asm volatile(
        "mma.sync.aligned.m16n8k16.row.col.f32.bf16.bf16.f32 "
        "{%0,%1,%2,%3}, {%4,%5,%6,%7}, {%8,%9}, {%0,%1,%2,%3};"
        : "+f"(d[0]), "+f"(d[1]), "+f"(d[2]), "+f"(d[3])
        : "r"(a[0]), "r"(a[1]), "r"(a[2]), "r"(a[3]), "r"(b0), "r"(b1));
}
// split one fp32x4 into packed bf16 hi-pair / lo-pair words
__device__ __forceinline__ void split4(const float4 v, uint2& hi, uint2& lo) {
    __nv_bfloat16 h0 = __float2bfloat16(v.x), h1 = __float2bfloat16(v.y);
    __nv_bfloat16 h2 = __float2bfloat16(v.z), h3 = __float2bfloat16(v.w);
    __nv_bfloat16 l0 = __float2bfloat16(v.x - __bfloat162float(h0));
    __nv_bfloat16 l1 = __float2bfloat16(v.y - __bfloat162float(h1));
    __nv_bfloat16 l2 = __float2bfloat16(v.z - __bfloat162float(h2));
    __nv_bfloat16 l3 = __float2bfloat16(v.w - __bfloat162float(h3));
    hi.x = (uint32_t)__bfloat16_as_ushort(h0) |
           ((uint32_t)__bfloat16_as_ushort(h1) << 16);
    hi.y = (uint32_t)__bfloat16_as_ushort(h2) |
           ((uint32_t)__bfloat16_as_ushort(h3) << 16);
    lo.x = (uint32_t)__bfloat16_as_ushort(l0) |
           ((uint32_t)__bfloat16_as_ushort(l1) << 16);
    lo.y = (uint32_t)__bfloat16_as_ushort(l2) |
           ((uint32_t)__bfloat16_as_ushort(l3) << 16);
}

// ---------------------------------------------------------------------------
// Kernel 1: x_proj via bf16 hi/lo-split HMMA (UNCHANGED, passing)
// ---------------------------------------------------------------------------
#define XS_ROW   80
#define XS_BUF   (128 * XS_ROW)
__global__ void __launch_bounds__(256, 1) xproj_mma_kernel(
    const float* __restrict__ A, const float* __restrict__ W,
    const float* __restrict__ bih, const float* __restrict__ bhh)
{
    __shared__ __align__(16) char sAH[XS_BUF];
    __shared__ __align__(16) char sAL[XS_BUF];
    __shared__ __align__(16) char sWH[XS_BUF];
    __shared__ __align__(16) char sWL[XS_BUF];
    __shared__ float sBias[128];

    const int tid = threadIdx.x;
    const int n0 = blockIdx.x * 128;
    const int m0 = blockIdx.y * 128;
    const int lane = tid & 31, wid = tid >> 5;
    const int wm = wid >> 1, wn = wid & 1;

    if (tid < 128) sBias[tid] = bih[n0 + tid] + bhh[n0 + tid];

    const int srow = tid >> 3;
    const int sc4  = (tid & 7) << 2;
    const float* agp = A + (size_t)(m0 + srow) * IDIM + sc4;
    const float* wgp = W + (size_t)(n0 + srow) * IDIM + sc4;

    const int lr = lane & 7, sel = lane >> 3;
    const int koff2 = ((sel >> 1) * 8) * 2;
    const uint32_t aH = smem_u32(sAH) + (uint32_t)(wm * 32 + (sel & 1) * 8 + lr) * XS_ROW + koff2;
    const uint32_t aL = smem_u32(sAL) + (uint32_t)(wm * 32 + (sel & 1) * 8 + lr) * XS_ROW + koff2;
    const uint32_t bH = smem_u32(sWH) + (uint32_t)(wn * 64 + (sel & 1) * 8 + lr) * XS_ROW + koff2;
    const uint32_t bL = smem_u32(sWL) + (uint32_t)(wn * 64 + (sel & 1) * 8 + lr) * XS_ROW + koff2;

    float d[2][8][4];
#pragma unroll
    for (int i = 0; i < 2; i++)
#pragma unroll
        for (int j = 0; j < 8; j++)
#pragma unroll
            for (int q = 0; q < 4; q++) d[i][j][q] = 0.0f;

    float4 pfA[4], pfW[4];
#pragma unroll
    for (int i = 0; i < 4; i++) {
        pfA[i] = *(const float4*)(agp + i * 32 * IDIM);
        pfW[i] = *(const float4*)(wgp + i * 32 * IDIM);
    }

    for (int kc = 0; kc < 16; kc++) {
#pragma unroll
        for (int i = 0; i < 4; i++) {
            int row = srow + i * 32;
            uint2 hi, lo;
            split4(pfA[i], hi, lo);
            *(uint2*)(sAH + row * XS_ROW + sc4 * 2) = hi;
            *(uint2*)(sAL + row * XS_ROW + sc4 * 2) = lo;
            split4(pfW[i], hi, lo);
            *(uint2*)(sWH + row * XS_ROW + sc4 * 2) = hi;
            *(uint2*)(sWL + row * XS_ROW + sc4 * 2) = lo;
        }
        __syncthreads();

        if (kc < 15) {
            const float* an = agp + (kc + 1) * 32;
            const float* wnp = wgp + (kc + 1) * 32;
#pragma unroll
            for (int i = 0; i < 4; i++) {
                pfA[i] = *(const float4*)(an + i * 32 * IDIM);
                pfW[i] = *(const float4*)(wnp + i * 32 * IDIM);
            }
        }

#pragma unroll
        for (int k16 = 0; k16 < 2; k16++) {
            const uint32_t ko = (uint32_t)(k16 * 32);
            uint32_t ah[2][4], al[2][4];
            ldm4(ah[0], aH + ko);
            ldm4(ah[1], aH + ko + 16 * XS_ROW);
            ldm4(al[0], aL + ko);
            ldm4(al[1], aL + ko + 16 * XS_ROW);
#pragma unroll
            for (int bnp = 0; bnp < 4; bnp++) {
                uint32_t bh[4], bl[4];
                ldm4(bh, bH + ko + (uint32_t)(bnp * 16) * XS_ROW);
                mma16816(d[0][2 * bnp],     ah[0], bh[0], bh[2]);
                mma16816(d[0][2 * bnp + 1], ah[0], bh[1], bh[3]);
                mma16816(d[1][2 * bnp],     ah[1], bh[0], bh[2]);
                mma16816(d[1][2 * bnp + 1], ah[1], bh[1], bh[3]);
                mma16816(d[0][2 * bnp],     al[0], bh[0], bh[2]);
                mma16816(d[0][2 * bnp + 1], al[0], bh[1], bh[3]);
                mma16816(d[1][2 * bnp],     al[1], bh[0], bh[2]);
                mma16816(d[1][2 * bnp + 1], al[1], bh[1], bh[3]);
                ldm4(bl, bL + ko + (uint32_t)(bnp * 16) * XS_ROW);
                mma16816(d[0][2 * bnp],     ah[0], bl[0], bl[2]);
                mma16816(d[0][2 * bnp + 1], ah[0], bl[1], bl[3]);
                mma16816(d[1][2 * bnp],     ah[1], bl[0], bl[2]);
                mma16816(d[1][2 * bnp + 1], ah[1], bl[1], bl[3]);
            }
        }
        __syncthreads();
    }

    const int erow = m0 + wm * 32 + (lane >> 2);
    const int ecol = wn * 64 + (lane & 3) * 2;
#pragma unroll
    for (int am = 0; am < 2; am++) {
#pragma unroll
        for (int bn = 0; bn < 8; bn++) {
            int col = ecol + bn * 8;
            float b0 = sBias[col], b1 = sBias[col + 1];
            float* p0 = g_xproj + (size_t)(erow + am * 16) * G4 + n0 + col;
            float* p1 = p0 + 8 * G4;
            *(float2*)p0 = make_float2(d[am][bn][0] + b0, d[am][bn][1] + b1);
            *(float2*)p1 = make_float2(d[am][bn][2] + b0, d[am][bn][3] + b1);
        }
    }
}

// ---------------------------------------------------------------------------
// Kernel 2: recurrence with W_hh fragments register-resident.
// Grid (32 col-groups, 4 batch-groups). CTA: 16 batches x 16 h-cols
// (64 gate rows, row = gate*16+jj). 16 warps = kw(8 K-slices of 64) x nw(2
// n-slices of 32). Per step per warp: 8 ldm4 (A hi/lo) + 48 MMA; B from regs.
// Barrier: red.release.gpu + ld.acquire.gpu poll (per batch-group, 32 CTAs).
// ---------------------------------------------------------------------------
#define OFF_WHI  0                         // 64 rows x 1040 B
#define OFF_WLO  66560
#define OFF_HHI  133120                    // 16 rows x 1040 B
#define OFF_HLO  149760
#define OFF_XP   166400                    // float [16][64]
#define OFF_P9   170496                    // float [16*64][12]  (49152 B)
#define OFF_C    219648                    // float [256]
#define R_SMEM   220672

__global__ void __launch_bounds__(512, 1) recur_mma_kernel(
    const float* __restrict__ h0, const float* __restrict__ c0,
    const float* __restrict__ Whh, float* __restrict__ out)
{
    extern __shared__ char sm[];
    float* xp_s = (float*)(sm + OFF_XP);
    float* p9   = (float*)(sm + OFF_P9);
    float* c_s  = (float*)(sm + OFF_C);

    const int tid  = threadIdx.x;
    const int lane = tid & 31, wid = tid >> 5;
    const int kw = wid >> 1;               // K slice of 64 (0..7)
    const int nw = wid & 1;                // n slice of 32 (0..1)
    const int j0 = blockIdx.x * 16;
    const int B0 = blockIdx.y * 16;
    const int grp = blockIdx.y;
    unsigned int* flag = &g_bar4[grp * 32];

    // ---- convert W_hh slice to bf16 hi/lo in SMEM (once) ----
#pragma unroll 4
    for (int i = 0; i < 16; i++) {
        int idx = tid + i * 512;
        int row = idx >> 7;                // 0..63 (gate*16+jj)
        int f4  = (idx & 127) << 2;
        int gate = row >> 4, jj = row & 15;
        float4 v = *(const float4*)(Whh
                      + (size_t)(gate * HDIM + j0 + jj) * HDIM + f4);
        uint2 hi, lo;
        split4(v, hi, lo);
        *(uint2*)(sm + OFF_WHI + row * 1040 + f4 * 2) = hi;
        *(uint2*)(sm + OFF_WLO + row * 1040 + f4 * 2) = lo;
    }
    if (tid < 256)
        c_s[tid] = c0[(size_t)(B0 + (tid >> 4)) * HDIM + j0 + (tid & 15)];
    __syncthreads();

    // ---- load B (W) fragments into registers (once) ----
    const int lr = lane & 7, sel = lane >> 3;
    uint32_t BH[4][2][4], BL[4][2][4];
#pragma unroll
    for (int ks = 0; ks < 4; ks++)
#pragma unroll
        for (int p = 0; p < 2; p++) {
            uint32_t off = (uint32_t)(nw * 32 + p * 16 + (sel & 1) * 8 + lr) * 1040u
                         + (uint32_t)((sel >> 1) * 16)
                         + (uint32_t)(kw * 128 + ks * 32);
            ldm4(BH[ks][p], smem_u32(sm + OFF_WHI) + off);
            ldm4(BL[ks][p], smem_u32(sm + OFF_WLO) + off);
        }

    // ---- A (h) ldmatrix addressing ----
    const uint32_t aRowOff = (uint32_t)((sel & 1) * 8 + lr) * 1040u
                           + (uint32_t)((sel >> 1) * 16)
                           + (uint32_t)(kw * 128);
    const uint32_t aHiB = smem_u32(sm + OFF_HHI) + aRowOff;
    const uint32_t aLoB = smem_u32(sm + OFF_HLO) + aRowOff;

    for (int t = T_STEPS - 1; t >= 0; t--) {
        // ---- prefetch x_proj slice (DRAM latency hides under poll) ----
        float4 xv;
        if (tid < 256) {
            int b = tid >> 4, q = tid & 15;
            int g = q >> 2, f = q & 3;
            xv = *(const float4*)(g_xproj
                    + ((size_t)t * BATCH + B0 + b) * G4
                    + g * HDIM + j0 + f * 4);
        }
        // ---- acquire-poll group barrier (all threads) ----
        if (t < T_STEPS - 1) {
            unsigned target = (unsigned)(T_STEPS - 1 - t) * 32u;
            unsigned v;
            do {
                asm volatile("ld.acquire.gpu.global.u32 %0, [%1];"
                             : "=r"(v) : "l"(flag) : "memory");
            } while (v < target);
        }

        // ---- stage h fp32 -> bf16 hi/lo ----
        const float* hsrc = (t == T_STEPS - 1)
                              ? (h0 + (size_t)B0 * HDIM)
                              : (out + (size_t)(t + 1) * (BATCH * HDIM)
                                     + (size_t)B0 * HDIM);
        {
            int r  = tid & 15;
            int cb = (tid >> 4) * 16;
            const float4* hp = (const float4*)(hsrc + r * HDIM + cb);
            float4 v0 = hp[0], v1 = hp[1], v2 = hp[2], v3 = hp[3];
            char* dH = sm + OFF_HHI + r * 1040 + cb * 2;
            char* dL = sm + OFF_HLO + r * 1040 + cb * 2;
            uint2 hi, lo;
            split4(v0, hi, lo); *(uint2*)(dH) = hi;      *(uint2*)(dL) = lo;
            split4(v1, hi, lo); *(uint2*)(dH + 8) = hi;  *(uint2*)(dL + 8) = lo;
            split4(v2, hi, lo); *(uint2*)(dH + 16) = hi; *(uint2*)(dL + 16) = lo;
            split4(v3, hi, lo); *(uint2*)(dH + 24) = hi; *(uint2*)(dL + 24) = lo;
            if (tid < 256) {
                int b = tid >> 4, q = tid & 15;
                int g = q >> 2, f = q & 3;
                *(float4*)(xp_s + b * 64 + g * 16 + f * 4) = xv;
            }
        }
        __syncthreads();

        // ---- MMA: 4 k16 steps, B from registers ----
        float acc[4][4];
#pragma unroll
        for (int q = 0; q < 4; q++)
#pragma unroll
            for (int i = 0; i < 4; i++) acc[q][i] = 0.0f;
#pragma unroll
        for (int ks = 0; ks < 4; ks++) {
            uint32_t ah[4], al[4];
            ldm4(ah, aHiB + (uint32_t)(ks * 32));
            ldm4(al, aLoB + (uint32_t)(ks * 32));
#pragma unroll
            for (int q = 0; q < 4; q++) {
                const int p = q >> 1, hh = q & 1;
                mma16816(acc[q], ah, BH[ks][p][hh], BH[ks][p][hh + 2]);
                mma16816(acc[q], al, BH[ks][p][hh], BH[ks][p][hh + 2]);
                mma16816(acc[q], ah, BL[ks][p][hh], BL[ks][p][hh + 2]);
            }
        }
        // ---- store partials: p9[(b*64+cc)*12 + kw] ----
        {
            const int r = lane >> 2;
            const int c2 = (lane & 3) * 2;
#pragma unroll
            for (int q = 0; q < 4; q++) {
                int cc = nw * 32 + q * 8 + c2;
                p9[((r    ) * 64 + cc    ) * 12 + kw] = acc[q][0];
                p9[((r    ) * 64 + cc + 1) * 12 + kw] = acc[q][1];
                p9[((r + 8) * 64 + cc    ) * 12 + kw] = acc[q][2];
                p9[((r + 8) * 64 + cc + 1) * 12 + kw] = acc[q][3];
            }
        }
        __syncthreads();

        // ---- reduce 8 K-slices + cell update (256 threads) ----
        if (tid < 256) {
            int b = tid >> 4, jj = tid & 15;
            float pre[4];
#pragma unroll
            for (int g = 0; g < 4; g++) {
                int cc = g * 16 + jj;
                const float* pp = p9 + (b * 64 + cc) * 12;
                float4 u = *(const float4*)pp;
                float4 w2 = *(const float4*)(pp + 4);
                pre[g] = ((u.x + u.y) + (u.z + u.w))
                       + ((w2.x + w2.y) + (w2.z + w2.w))
                       + xp_s[b * 64 + cc];
            }
            float gi = sigf(pre[0]);
            float gf = sigf(pre[1]);
            float gz = sigf(pre[2]);
            float go = sigf(pre[3]);
            float cn = gf * c_s[tid] + gz - gi;
            c_s[tid] = cn;
            float hn = sigf(cn) - go;
            out[(size_t)t * (BATCH * HDIM) + (size_t)(B0 + b) * HDIM + j0 + jj] = hn;
            if (t == 0) {
                const size_t base = (size_t)T_STEPS * BATCH * HDIM;
                out[base + (size_t)(B0 + b) * HDIM + j0 + jj] = hn;
                out[base + BATCH * HDIM + (size_t)(B0 + b) * HDIM + j0 + jj] = cn;
            }
        }
        __syncthreads();

        // ---- release: publish h writes, bump group flag ----
        if (t > 0 && tid == 0) {
            asm volatile("red.release.gpu.global.add.u32 [%0], %1;"
                         :: "l"(flag), "r"(1u) : "memory");
        }
    }

    // ---- self-reset of counters (after ALL 128 CTAs finish) ----
    __syncthreads();
    if (tid == 0) {
        unsigned v = atomicAdd(&g_done, 1u);
        if (v == 127u) {
            atomicExch(&g_bar4[0], 0u);
            atomicExch(&g_bar4[32], 0u);
            atomicExch(&g_bar4[64], 0u);
            atomicExch(&g_bar4[96], 0u);
            atomicExch(&g_done, 0u);
        }
    }
}

// ---------------------------------------------------------------------------
extern "C" void kernel_launch(void* const* d_in, const int* in_sizes, int n_in,
                              void* d_out, int out_size)
{
    const float* input = (const float*)d_in[0];
    const float* h0    = (const float*)d_in[1];
    const float* c0    = (const float*)d_in[2];
    const float* Wih   = (const float*)d_in[3];
    const float* Whh   = (const float*)d_in[4];
    const float* bih   = (const float*)d_in[5];
    const float* bhh   = (const float*)d_in[6];
    float* out = (float*)d_out;

    static int configured = 0;
    if (!configured) {
        cudaFuncSetAttribute(recur_mma_kernel,
                             cudaFuncAttributeMaxDynamicSharedMemorySize,
                             R_SMEM);
        configured = 1;
    }

    xproj_mma_kernel<<<dim3(G4 / 128, MTOT / 128), 256>>>(input, Wih, bih, bhh);
    recur_mma_kernel<<<dim3(HDIM / 16, BATCH / 16), 512, R_SMEM>>>(
        h0, c0, Whh, out);
}

// round 9
// speedup vs baseline: 1.9312x; 1.1138x over previous
#include <cuda_runtime.h>
#include <cuda_bf16.h>
#include <math.h>
#include <stdint.h>

#define T_STEPS 1024
#define BATCH   64
#define IDIM    512
#define HDIM    512
#define G4      2048   // 4*H
#define MTOT    (T_STEPS * BATCH)   // 65536

// ---- device-global scratch (no allocs allowed) ----
__device__ float        g_xproj[(size_t)MTOT * G4];   // 512 MB
__device__ uint32_t     g_hpack[BATCH * HDIM];        // packed bf16 hi|lo of h
__device__ unsigned int g_bar4[4 * 32];               // per-batch-group flags
__device__ unsigned int g_done;

__device__ __forceinline__ float sigf(float x) {
    return __fdividef(1.0f, 1.0f + __expf(-x));
}

// ---------------- mma.sync helpers (baseline PTX, no 'a' features) ----------
__device__ __forceinline__ uint32_t smem_u32(const void* p) {
    uint32_t a;
    asm("{ .reg .u64 t; cvta.to.shared.u64 t, %1; cvt.u32.u64 %0, t; }"
        : "=r"(a) : "l"(p));
    return a;
}
__device__ __forceinline__ uint32_t prmt(uint32_t a, uint32_t b, uint32_t s) {
    uint32_t r;
    asm("prmt.b32 %0, %1, %2, %3;" : "=r"(r) : "r"(a), "r"(b), "r"(s));
    return r;
}
__device__ __forceinline__ void ldm4(uint32_t* r, uint32_t addr) {
    asm volatile("ldmatrix.sync.aligned.m8n8.x4.shared.b16 {%0,%1,%2,%3}, [%4];"
                 : "=r"(r[0]), "=r"(r[1]), "=r"(r[2]), "=r"(r[3]) : "r"(addr));
}
__device__ __forceinline__ void mma16816(float* d, const uint32_t* a,
                                         uint32_t b0, uint32_t b1) {
    asm volatile(
        "mma.sync.aligned.m16n8k16.row.col.f32.bf16.bf16.f32 "
        "{%0,%1,%2,%3}, {%4,%5,%6,%7}, {%8,%9}, {%0,%1,%2,%3};"
        : "+f"(d[0]), "+f"(d[1]), "+f"(d[2]), "+f"(d[3])
        : "r"(a[0]), "r"(a[1]), "r"(a[2]), "r"(a[3]), "r"(b0), "r"(b1));
}
// split one fp32x4 into packed bf16 hi-pair / lo-pair words
__device__ __forceinline__ void split4(const float4 v, uint2& hi, uint2& lo) {
    __nv_bfloat16 h0 = __float2bfloat16(v.x), h1 = __float2bfloat16(v.y);
    __nv_bfloat16 h2 = __float2bfloat16(v.z), h3 = __float2bfloat16(v.w);
    __nv_bfloat16 l0 = __float2bfloat16(v.x - __bfloat162float(h0));
    __nv_bfloat16 l1 = __float2bfloat16(v.y - __bfloat162float(h1));
    __nv_bfloat16 l2 = __float2bfloat16(v.z - __bfloat162float(h2));
    __nv_bfloat16 l3 = __float2bfloat16(v.w - __bfloat162float(h3));
    hi.x = (uint32_t)__bfloat16_as_ushort(h0) |
           ((uint32_t)__bfloat16_as_ushort(h1) << 16);
    hi.y = (uint32_t)__bfloat16_as_ushort(h2) |
           ((uint32_t)__bfloat16_as_ushort(h3) << 16);
    lo.x = (uint32_t)__bfloat16_as_ushort(l0) |
           ((uint32_t)__bfloat16_as_ushort(l1) << 16);
    lo.y = (uint32_t)__bfloat16_as_ushort(l2) |
           ((uint32_t)__bfloat16_as_ushort(l3) << 16);
}
__device__ __forceinline__ uint32_t pack_hilo(float v) {
    __nv_bfloat16 h = __float2bfloat16(v);
    __nv_bfloat16 l = __float2bfloat16(v - __bfloat162float(h));
    return (uint32_t)__bfloat16_as_ushort(h) |
           ((uint32_t)__bfloat16_as_ushort(l) << 16);
}

// ---------------------------------------------------------------------------
// Kernel 0: pre-pack h0 into g_hpack (keeps the recurrence loop uniform).
// ---------------------------------------------------------------------------
__global__ void pack_h0_kernel(const float* __restrict__ h0) {
    int i = blockIdx.x * blockDim.x + threadIdx.x;
    if (i < BATCH * HDIM) g_hpack[i] = pack_hilo(h0[i]);
}

// ---------------------------------------------------------------------------
// Kernel 1: x_proj via bf16 hi/lo-split HMMA (UNCHANGED, passing)
// ---------------------------------------------------------------------------
#define XS_ROW   80
#define XS_BUF   (128 * XS_ROW)
__global__ void __launch_bounds__(256, 1) xproj_mma_kernel(
    const float* __restrict__ A, const float* __restrict__ W,
    const float* __restrict__ bih, const float* __restrict__ bhh)
{
    __shared__ __align__(16) char sAH[XS_BUF];
    __shared__ __align__(16) char sAL[XS_BUF];
    __shared__ __align__(16) char sWH[XS_BUF];
    __shared__ __align__(16) char sWL[XS_BUF];
    __shared__ float sBias[128];

    const int tid = threadIdx.x;
    const int n0 = blockIdx.x * 128;
    const int m0 = blockIdx.y * 128;
    const int lane = tid & 31, wid = tid >> 5;
    const int wm = wid >> 1, wn = wid & 1;

    if (tid < 128) sBias[tid] = bih[n0 + tid] + bhh[n0 + tid];

    const int srow = tid >> 3;
    const int sc4  = (tid & 7) << 2;
    const float* agp = A + (size_t)(m0 + srow) * IDIM + sc4;
    const float* wgp = W + (size_t)(n0 + srow) * IDIM + sc4;

    const int lr = lane & 7, sel = lane >> 3;
    const int koff2 = ((sel >> 1) * 8) * 2;
    const uint32_t aH = smem_u32(sAH) + (uint32_t)(wm * 32 + (sel & 1) * 8 + lr) * XS_ROW + koff2;
    const uint32_t aL = smem_u32(sAL) + (uint32_t)(wm * 32 + (sel & 1) * 8 + lr) * XS_ROW + koff2;
    const uint32_t bH = smem_u32(sWH) + (uint32_t)(wn * 64 + (sel & 1) * 8 + lr) * XS_ROW + koff2;
    const uint32_t bL = smem_u32(sWL) + (uint32_t)(wn * 64 + (sel & 1) * 8 + lr) * XS_ROW + koff2;

    float d[2][8][4];
#pragma unroll
    for (int i = 0; i < 2; i++)
#pragma unroll
        for (int j = 0; j < 8; j++)
#pragma unroll
            for (int q = 0; q < 4; q++) d[i][j][q] = 0.0f;

    float4 pfA[4], pfW[4];
#pragma unroll
    for (int i = 0; i < 4; i++) {
        pfA[i] = *(const float4*)(agp + i * 32 * IDIM);
        pfW[i] = *(const float4*)(wgp + i * 32 * IDIM);
    }

    for (int kc = 0; kc < 16; kc++) {
#pragma unroll
        for (int i = 0; i < 4; i++) {
            int row = srow + i * 32;
            uint2 hi, lo;
            split4(pfA[i], hi, lo);
            *(uint2*)(sAH + row * XS_ROW + sc4 * 2) = hi;
            *(uint2*)(sAL + row * XS_ROW + sc4 * 2) = lo;
            split4(pfW[i], hi, lo);
            *(uint2*)(sWH + row * XS_ROW + sc4 * 2) = hi;
            *(uint2*)(sWL + row * XS_ROW + sc4 * 2) = lo;
        }
        __syncthreads();

        if (kc < 15) {
            const float* an = agp + (kc + 1) * 32;
            const float* wnp = wgp + (kc + 1) * 32;
#pragma unroll
            for (int i = 0; i < 4; i++) {
                pfA[i] = *(const float4*)(an + i * 32 * IDIM);
                pfW[i] = *(const float4*)(wnp + i * 32 * IDIM);
            }
        }

#pragma unroll
        for (int k16 = 0; k16 < 2; k16++) {
            const uint32_t ko = (uint32_t)(k16 * 32);
            uint32_t ah[2][4], al[2][4];
            ldm4(ah[0], aH + ko);
            ldm4(ah[1], aH + ko + 16 * XS_ROW);
            ldm4(al[0], aL + ko);
            ldm4(al[1], aL + ko + 16 * XS_ROW);
#pragma unroll
            for (int bnp = 0; bnp < 4; bnp++) {
                uint32_t bh[4], bl[4];
                ldm4(bh, bH + ko + (uint32_t)(bnp * 16) * XS_ROW);
                mma16816(d[0][2 * bnp],     ah[0], bh[0], bh[2]);
                mma16816(d[0][2 * bnp + 1], ah[0], bh[1], bh[3]);
                mma16816(d[1][2 * bnp],     ah[1], bh[0], bh[2]);
                mma16816(d[1][2 * bnp + 1], ah[1], bh[1], bh[3]);
                mma16816(d[0][2 * bnp],     al[0], bh[0], bh[2]);
                mma16816(d[0][2 * bnp + 1], al[0], bh[1], bh[3]);
                mma16816(d[1][2 * bnp],     al[1], bh[0], bh[2]);
                mma16816(d[1][2 * bnp + 1], al[1], bh[1], bh[3]);
                ldm4(bl, bL + ko + (uint32_t)(bnp * 16) * XS_ROW);
                mma16816(d[0][2 * bnp],     ah[0], bl[0], bl[2]);
                mma16816(d[0][2 * bnp + 1], ah[0], bl[1], bl[3]);
                mma16816(d[1][2 * bnp],     ah[1], bl[0], bl[2]);
                mma16816(d[1][2 * bnp + 1], ah[1], bl[1], bl[3]);
            }
        }
        __syncthreads();
    }

    const int erow = m0 + wm * 32 + (lane >> 2);
    const int ecol = wn * 64 + (lane & 3) * 2;
#pragma unroll
    for (int am = 0; am < 2; am++) {
#pragma unroll
        for (int bn = 0; bn < 8; bn++) {
            int col = ecol + bn * 8;
            float b0 = sBias[col], b1 = sBias[col + 1];
            float* p0 = g_xproj + (size_t)(erow + am * 16) * G4 + n0 + col;
            float* p1 = p0 + 8 * G4;
            *(float2*)p0 = make_float2(d[am][bn][0] + b0, d[am][bn][1] + b1);
            *(float2*)p1 = make_float2(d[am][bn][2] + b0, d[am][bn][3] + b1);
        }
    }
}

// ---------------------------------------------------------------------------
// Kernel 2: recurrence. W fragments in registers; h published pre-split in
// g_hpack (u32 = bf16 hi | bf16 lo<<16); warp-15-only poll; per-cell-warp
// early release; conflict-fixed partials [kw][b*68+cc] (plane stride 1092).
// ---------------------------------------------------------------------------
#define OFF_WHI  0                         // 64 rows x 1040 B
#define OFF_WLO  66560
#define OFF_HHI  133120                    // 16 rows x 1040 B
#define OFF_HLO  149760
#define OFF_XP   166400                    // float [16][64]
#define OFF_P9   170496                    // float [8][1092]  (34944 B)
#define OFF_C    205440                    // float [256]
#define R_SMEM   206464

__global__ void __launch_bounds__(512, 1) recur_mma_kernel(
    const float* __restrict__ h0, const float* __restrict__ c0,
    const float* __restrict__ Whh, float* __restrict__ out)
{
    extern __shared__ char sm[];
    float* xp_s = (float*)(sm + OFF_XP);
    float* p9   = (float*)(sm + OFF_P9);
    float* c_s  = (float*)(sm + OFF_C);

    const int tid  = threadIdx.x;
    const int lane = tid & 31, wid = tid >> 5;
    const int kw = wid >> 1;               // K slice of 64 (0..7)
    const int nw = wid & 1;                // n slice of 32 (0..1)
    const int j0 = blockIdx.x * 16;
    const int B0 = blockIdx.y * 16;
    const int grp = blockIdx.y;
    unsigned int* flag = &g_bar4[grp * 32];

    // ---- convert W_hh slice to bf16 hi/lo in SMEM (once) ----
#pragma unroll 4
    for (int i = 0; i < 16; i++) {
        int idx = tid + i * 512;
        int row = idx >> 7;                // 0..63 (gate*16+jj)
        int f4  = (idx & 127) << 2;
        int gate = row >> 4, jj = row & 15;
        float4 v = *(const float4*)(Whh
                      + (size_t)(gate * HDIM + j0 + jj) * HDIM + f4);
        uint2 hi, lo;
        split4(v, hi, lo);
        *(uint2*)(sm + OFF_WHI + row * 1040 + f4 * 2) = hi;
        *(uint2*)(sm + OFF_WLO + row * 1040 + f4 * 2) = lo;
    }
    if (tid < 256)
        c_s[tid] = c0[(size_t)(B0 + (tid >> 4)) * HDIM + j0 + (tid & 15)];
    __syncthreads();

    // ---- load B (W) fragments into registers (once) ----
    const int lr = lane & 7, sel = lane >> 3;
    uint32_t BH[4][2][4], BL[4][2][4];
#pragma unroll
    for (int ks = 0; ks < 4; ks++)
#pragma unroll
        for (int p = 0; p < 2; p++) {
            uint32_t off = (uint32_t)(nw * 32 + p * 16 + (sel & 1) * 8 + lr) * 1040u
                         + (uint32_t)((sel >> 1) * 16)
                         + (uint32_t)(kw * 128 + ks * 32);
            ldm4(BH[ks][p], smem_u32(sm + OFF_WHI) + off);
            ldm4(BL[ks][p], smem_u32(sm + OFF_WLO) + off);
        }

    // ---- A (h) ldmatrix addressing ----
    const uint32_t aRowOff = (uint32_t)((sel & 1) * 8 + lr) * 1040u
                           + (uint32_t)((sel >> 1) * 16)
                           + (uint32_t)(kw * 128);
    const uint32_t aHiB = smem_u32(sm + OFF_HHI) + aRowOff;
    const uint32_t aLoB = smem_u32(sm + OFF_HLO) + aRowOff;

    // staging map: thread -> row r (batch), 16 packed u32 cols at cb
    const int sr  = tid & 15;
    const int scb = (tid >> 4) * 16;
    const uint4* hgp = (const uint4*)(g_hpack + (B0 + sr) * HDIM + scb);
    char* dH = sm + OFF_HHI + sr * 1040 + scb * 2;
    char* dL = sm + OFF_HLO + sr * 1040 + scb * 2;

    for (int t = T_STEPS - 1; t >= 0; t--) {
        // ---- prefetch x_proj slice (DRAM latency hides under poll wait) ----
        float4 xv;
        if (tid < 256) {
            int b = tid >> 4, q = tid & 15;
            int g = q >> 2, f = q & 3;
            xv = *(const float4*)(g_xproj
                    + ((size_t)t * BATCH + B0 + b) * G4
                    + g * HDIM + j0 + f * 4);
        }
        // ---- warp 15 polls; everyone gates on syncthreads ----
        if (t < T_STEPS - 1 && wid == 15) {
            unsigned target = (unsigned)(T_STEPS - 1 - t) * 256u;
            unsigned v;
            do {
                asm volatile("ld.acquire.gpu.global.u32 %0, [%1];"
                             : "=r"(v) : "l"(flag) : "memory");
            } while (v < target);
        }
        __syncthreads();

        // ---- stage h: unpack packed hi|lo with prmt (no CVT chain) ----
        {
            uint4 p0 = hgp[0], p1 = hgp[1], p2 = hgp[2], p3 = hgp[3];
            uint2 h_, l_;
            h_.x = prmt(p0.x, p0.y, 0x5410); l_.x = prmt(p0.x, p0.y, 0x7632);
            h_.y = prmt(p0.z, p0.w, 0x5410); l_.y = prmt(p0.z, p0.w, 0x7632);
            *(uint2*)(dH +  0) = h_; *(uint2*)(dL +  0) = l_;
            h_.x = prmt(p1.x, p1.y, 0x5410); l_.x = prmt(p1.x, p1.y, 0x7632);
            h_.y = prmt(p1.z, p1.w, 0x5410); l_.y = prmt(p1.z, p1.w, 0x7632);
            *(uint2*)(dH +  8) = h_; *(uint2*)(dL +  8) = l_;
            h_.x = prmt(p2.x, p2.y, 0x5410); l_.x = prmt(p2.x, p2.y, 0x7632);
            h_.y = prmt(p2.z, p2.w, 0x5410); l_.y = prmt(p2.z, p2.w, 0x7632);
            *(uint2*)(dH + 16) = h_; *(uint2*)(dL + 16) = l_;
            h_.x = prmt(p3.x, p3.y, 0x5410); l_.x = prmt(p3.x, p3.y, 0x7632);
            h_.y = prmt(p3.z, p3.w, 0x5410); l_.y = prmt(p3.z, p3.w, 0x7632);
            *(uint2*)(dH + 24) = h_; *(uint2*)(dL + 24) = l_;
            if (tid < 256) {
                int b = tid >> 4, q = tid & 15;
                int g = q >> 2, f = q & 3;
                *(float4*)(xp_s + b * 64 + g * 16 + f * 4) = xv;
            }
        }
        __syncthreads();

        // ---- MMA: 4 k16 steps, B from registers ----
        float acc[4][4];
#pragma unroll
        for (int q = 0; q < 4; q++)
#pragma unroll
            for (int i = 0; i < 4; i++) acc[q][i] = 0.0f;
#pragma unroll
        for (int ks = 0; ks < 4; ks++) {
            uint32_t ah[4], al[4];
            ldm4(ah, aHiB + (uint32_t)(ks * 32));
            ldm4(al, aLoB + (uint32_t)(ks * 32));
#pragma unroll
            for (int q = 0; q < 4; q++) {
                const int p = q >> 1, hh = q & 1;
                mma16816(acc[q], ah, BH[ks][p][hh], BH[ks][p][hh + 2]);
                mma16816(acc[q], al, BH[ks][p][hh], BH[ks][p][hh + 2]);
                mma16816(acc[q], ah, BL[ks][p][hh], BL[ks][p][hh + 2]);
            }
        }
        // ---- store partials: p9[kw][b*68 + cc], STS.64, ~2-way conflicts ----
        {
            const int r = lane >> 2;
            const int c2 = (lane & 3) * 2;
            float* base = p9 + kw * 1092;
#pragma unroll
            for (int q = 0; q < 4; q++) {
                int cc = nw * 32 + q * 8 + c2;
                *(float2*)(base + r * 68 + cc)       = make_float2(acc[q][0], acc[q][1]);
                *(float2*)(base + (r + 8) * 68 + cc) = make_float2(acc[q][2], acc[q][3]);
            }
        }
        __syncthreads();

        // ---- reduce 8 K-slices + cell update (256 threads), early release ----
        if (tid < 256) {
            int b = tid >> 4, jj = tid & 15;
            float pre[4];
#pragma unroll
            for (int g = 0; g < 4; g++) {
                int off = b * 68 + g * 16 + jj;
                float s0 = p9[off]          + p9[1092 + off];
                float s1 = p9[2 * 1092 + off] + p9[3 * 1092 + off];
                float s2 = p9[4 * 1092 + off] + p9[5 * 1092 + off];
                float s3 = p9[6 * 1092 + off] + p9[7 * 1092 + off];
                pre[g] = ((s0 + s1) + (s2 + s3)) + xp_s[b * 64 + g * 16 + jj];
            }
            float gi = sigf(pre[0]);
            float gf = sigf(pre[1]);
            float gz = sigf(pre[2]);
            float go = sigf(pre[3]);
            float cn = gf * c_s[tid] + gz - gi;
            c_s[tid] = cn;
            float hn = sigf(cn) - go;
            out[(size_t)t * (BATCH * HDIM) + (size_t)(B0 + b) * HDIM + j0 + jj] = hn;
            g_hpack[(B0 + b) * HDIM + j0 + jj] = pack_hilo(hn);
            if (t == 0) {
                const size_t base = (size_t)T_STEPS * BATCH * HDIM;
                out[base + (size_t)(B0 + b) * HDIM + j0 + jj] = hn;
                out[base + BATCH * HDIM + (size_t)(B0 + b) * HDIM + j0 + jj] = cn;
            }
            __syncwarp();
            if (lane == 0 && t > 0) {
                asm volatile("red.release.gpu.global.add.u32 [%0], %1;"
                             :: "l"(flag), "r"(1u) : "memory");
            }
        }
    }

    // ---- self-reset of counters (after ALL 128 CTAs finish) ----
    __syncthreads();
    if (tid == 0) {
        unsigned v = atomicAdd(&g_done, 1u);
        if (v == 127u) {
            atomicExch(&g_bar4[0], 0u);
            atomicExch(&g_bar4[32], 0u);
            atomicExch(&g_bar4[64], 0u);
            atomicExch(&g_bar4[96], 0u);
            atomicExch(&g_done, 0u);
        }
    }
}

// ---------------------------------------------------------------------------
extern "C" void kernel_launch(void* const* d_in, const int* in_sizes, int n_in,
                              void* d_out, int out_size)
{
    const float* input = (const float*)d_in[0];
    const float* h0    = (const float*)d_in[1];
    const float* c0    = (const float*)d_in[2];
    const float* Wih   = (const float*)d_in[3];
    const float* Whh   = (const float*)d_in[4];
    const float* bih   = (const float*)d_in[5];
    const float* bhh   = (const float*)d_in[6];
    float* out = (float*)d_out;

    static int configured = 0;
    if (!configured) {
        cudaFuncSetAttribute(recur_mma_kernel,
                             cudaFuncAttributeMaxDynamicSharedMemorySize,
                             R_SMEM);
        configured = 1;
    }

    pack_h0_kernel<<<(BATCH * HDIM + 255) / 256, 256>>>(h0);
    xproj_mma_kernel<<<dim3(G4 / 128, MTOT / 128), 256>>>(input, Wih, bih, bhh);
    recur_mma_kernel<<<dim3(HDIM / 16, BATCH / 16), 512, R_SMEM>>>(
        h0, c0, Whh, out);
}